// round 5
// baseline (speedup 1.0000x reference)
#include <cuda_runtime.h>
#include <cuda_bf16.h>
#include <math.h>
#include <stdint.h>

// ---------------------------------------------------------------------------
// Problem constants
// ---------------------------------------------------------------------------
#define BB 32
#define SS 256
#define MM (BB*SS)        // 8192 rows
#define DD 768
#define HH 12
#define DHD 64
#define FFD 3072
#define LL 12
#define NSENSE 64
#define NATT 64
#define QKVN (3*DD)       // 2304

#define LW_QKVO ((size_t)DD*DD)
#define LW_FF   ((size_t)DD*FFD)
#define LWSTRIDE (4*LW_QKVO + 2*LW_FF)

// ---------------------------------------------------------------------------
// Scratch (static __device__ arrays; no runtime allocation allowed)
// ---------------------------------------------------------------------------
__device__ float g_x  [(size_t)MM*DD];         // residual stream (fp32)
__device__ float g_qkv[(size_t)MM*QKVN];       // fused QKV output (fp32)
__device__ float g_tmp[(size_t)MM*DD];         // gemm output before LN
__device__ float g_sk [NSENSE*NATT];
__device__ float g_cbias[LL*QKVN];             // concatenated qkv bias

__device__ __nv_bfloat16 g_wthi[LL*LWSTRIDE];     // transposed weights [N,K], hi
__device__ __nv_bfloat16 g_wtlo[LL*LWSTRIDE];     // transposed weights [N,K], lo
__device__ __nv_bfloat16 g_ahi [(size_t)MM*DD];   // activation hi (D-wide)
__device__ __nv_bfloat16 g_alo [(size_t)MM*DD];   // activation lo
__device__ __nv_bfloat16 g_bhi [(size_t)MM*FFD];  // ffn hidden hi
__device__ __nv_bfloat16 g_blo [(size_t)MM*FFD];  // ffn hidden lo

// ---------------------------------------------------------------------------
// asm helpers (sm_80-era features, legal on compute_103)
// ---------------------------------------------------------------------------
__device__ __forceinline__ uint32_t smem_to_u32(const void* smem_ptr) {
    uint32_t addr;
    asm("{ .reg .u64 tmp; cvta.to.shared.u64 tmp, %1; cvt.u32.u64 %0, tmp; }"
        : "=r"(addr) : "l"(smem_ptr));
    return addr;
}
#define CP_ASYNC16(dst_u32, src_ptr) \
    asm volatile("cp.async.cg.shared.global [%0], [%1], 16;" \
        :: "r"(dst_u32), "l"(src_ptr))
#define CP_COMMIT asm volatile("cp.async.commit_group;" ::: "memory")
#define CP_WAIT0  asm volatile("cp.async.wait_group 0;" ::: "memory")
#define CP_WAIT1  asm volatile("cp.async.wait_group 1;" ::: "memory")

__device__ __forceinline__ void ldsm_x4(uint32_t addr, uint32_t& r0, uint32_t& r1,
                                        uint32_t& r2, uint32_t& r3) {
    asm volatile("ldmatrix.sync.aligned.m8n8.x4.shared.b16 {%0,%1,%2,%3}, [%4];"
        : "=r"(r0), "=r"(r1), "=r"(r2), "=r"(r3) : "r"(addr));
}
__device__ __forceinline__ void ldsm_x2(uint32_t addr, uint32_t& r0, uint32_t& r1) {
    asm volatile("ldmatrix.sync.aligned.m8n8.x2.shared.b16 {%0,%1}, [%2];"
        : "=r"(r0), "=r"(r1) : "r"(addr));
}
__device__ __forceinline__ void mma_bf16(float* c, const uint32_t* a, const uint32_t* b) {
    asm volatile(
        "mma.sync.aligned.m16n8k16.row.col.f32.bf16.bf16.f32 "
        "{%0,%1,%2,%3}, {%4,%5,%6,%7}, {%8,%9}, {%0,%1,%2,%3};"
        : "+f"(c[0]), "+f"(c[1]), "+f"(c[2]), "+f"(c[3])
        : "r"(a[0]), "r"(a[1]), "r"(a[2]), "r"(a[3]), "r"(b[0]), "r"(b[1]));
}

__device__ __forceinline__ void split2(float f, __nv_bfloat16& h, __nv_bfloat16& l) {
    h = __float2bfloat16(f);
    l = __float2bfloat16(f - __bfloat162float(h));
}

// ---------------------------------------------------------------------------
// weight prep: transpose+split [K,N] fp32 -> [N,K] bf16 hi/lo
// ---------------------------------------------------------------------------
__global__ __launch_bounds__(256)
void transpose_split_kernel(const float* __restrict__ src,
                            __nv_bfloat16* __restrict__ dhi,
                            __nv_bfloat16* __restrict__ dlo, int K, int N)
{
    __shared__ float t[32][33];
    int tx = threadIdx.x, ty = threadIdx.y;   // block (32,8)
    int nx = blockIdx.x*32 + tx;
    int ky = blockIdx.y*32;
#pragma unroll
    for (int i = 0; i < 4; i++)
        t[ty + i*8][tx] = src[(size_t)(ky + ty + i*8)*N + nx];
    __syncthreads();
    int kx = blockIdx.y*32 + tx;
    int ny = blockIdx.x*32;
#pragma unroll
    for (int i = 0; i < 4; i++) {
        float f = t[tx][ty + i*8];
        __nv_bfloat16 h, l; split2(f, h, l);
        dhi[(size_t)(ny + ty + i*8)*K + kx] = h;
        dlo[(size_t)(ny + ty + i*8)*K + kx] = l;
    }
}

__global__ __launch_bounds__(256)
void concat_bias_kernel(const float* __restrict__ bq, const float* __restrict__ bk,
                        const float* __restrict__ bv, float* __restrict__ cb)
{
    int idx = blockIdx.x * 256 + threadIdx.x;
    if (idx >= LL * QKVN) return;
    int l = idx / QKVN, j = idx % QKVN;
    float v;
    if (j < DD)            v = bq[l*DD + j];
    else if (j < 2*DD)     v = bk[l*DD + j - DD];
    else                   v = bv[l*DD + j - 2*DD];
    cb[idx] = v;
}

// ---------------------------------------------------------------------------
// Embedding + LayerNorm -> x fp32 + (hi,lo) bf16 split
// ---------------------------------------------------------------------------
__global__ __launch_bounds__(256)
void embed_ln_kernel(const int* __restrict__ ids, const int* __restrict__ tt,
                     const float* __restrict__ we, const float* __restrict__ pe,
                     const float* __restrict__ te, const float* __restrict__ lg,
                     const float* __restrict__ lb, float* __restrict__ x,
                     __nv_bfloat16* __restrict__ xhi, __nv_bfloat16* __restrict__ xlo)
{
    int row = blockIdx.x;
    int s   = row % SS;
    int id  = ids[row];
    int t   = tt[row];
    int tid = threadIdx.x;
    const float* wr = we + (size_t)id * DD;
    const float* pr = pe + (size_t)s  * DD;
    const float* tr = te + (size_t)t  * DD;
    float v[3]; float sum = 0.f, sq = 0.f;
#pragma unroll
    for (int i = 0; i < 3; i++) {
        int d = tid + i * 256;
        float y = wr[d] + pr[d] + tr[d];
        v[i] = y; sum += y; sq += y * y;
    }
    __shared__ float sh1[256], sh2[256];
    sh1[tid] = sum; sh2[tid] = sq;
    __syncthreads();
    for (int st = 128; st > 0; st >>= 1) {
        if (tid < st) { sh1[tid] += sh1[tid+st]; sh2[tid] += sh2[tid+st]; }
        __syncthreads();
    }
    float mu  = sh1[0] * (1.f/768.f);
    float var = fmaxf(sh2[0] * (1.f/768.f) - mu*mu, 0.f);
    float inv = rsqrtf(var + 1e-12f);
#pragma unroll
    for (int i = 0; i < 3; i++) {
        int d = tid + i * 256;
        float y = (v[i]-mu)*inv*lg[d] + lb[d];
        size_t o = (size_t)row*DD + d;
        x[o] = y;
        __nv_bfloat16 h, l; split2(y, h, l);
        xhi[o] = h; xlo[o] = l;
    }
}

// ---------------------------------------------------------------------------
// Residual + bias + LayerNorm -> x fp32 (in place) + split
// ---------------------------------------------------------------------------
__global__ __launch_bounds__(256)
void ln_res_kernel(float* __restrict__ x, const float* __restrict__ val,
                   const float* __restrict__ bias, const float* __restrict__ lg,
                   const float* __restrict__ lb,
                   __nv_bfloat16* __restrict__ xhi, __nv_bfloat16* __restrict__ xlo)
{
    int row = blockIdx.x;
    int tid = threadIdx.x;
    float v[3]; float sum = 0.f, sq = 0.f;
#pragma unroll
    for (int i = 0; i < 3; i++) {
        int d = tid + i * 256;
        float y = x[(size_t)row*DD + d] + val[(size_t)row*DD + d] + bias[d];
        v[i] = y; sum += y; sq += y * y;
    }
    __shared__ float sh1[256], sh2[256];
    sh1[tid] = sum; sh2[tid] = sq;
    __syncthreads();
    for (int st = 128; st > 0; st >>= 1) {
        if (tid < st) { sh1[tid] += sh1[tid+st]; sh2[tid] += sh2[tid+st]; }
        __syncthreads();
    }
    float mu  = sh1[0] * (1.f/768.f);
    float var = fmaxf(sh2[0] * (1.f/768.f) - mu*mu, 0.f);
    float inv = rsqrtf(var + 1e-12f);
#pragma unroll
    for (int i = 0; i < 3; i++) {
        int d = tid + i * 256;
        float y = (v[i]-mu)*inv*lg[d] + lb[d];
        size_t o = (size_t)row*DD + d;
        x[o] = y;
        __nv_bfloat16 h, l; split2(y, h, l);
        xhi[o] = h; xlo[o] = l;
    }
}

// ---------------------------------------------------------------------------
// HMMA GEMM: C[M,N] = A[M,K] @ Bt[N,K]^T, 3-term bf16 split, fp32-equivalent.
// CTA 256x128x32, 8 warps (4m x 2n), warp tile 64x64, mma m16n8k16.
// 3-stage cp.async pipeline (180KB smem, 1 CTA/SM).
// MODE 0: C fp32            MODE 1: C fp32 + bias
// MODE 2: bias + gelu -> split bf16 outputs (Chi, Clo)
// ---------------------------------------------------------------------------
__device__ __forceinline__ float gelu_exact(float x) {
    return 0.5f * x * (1.0f + erff(x * 0.70710678118654752f));
}

#define GPAD 40                  // smem row stride (elements) -> 80 bytes
#define ATSZ (256*GPAD*2)        // 20480 B  (A tile: 256 x 32 bf16)
#define BTSZ (128*GPAD*2)        // 10240 B  (B tile: 128 x 32 bf16)
#define STAGEB (2*ATSZ + 2*BTSZ) // 61440 B: Ahi, Alo, Bhi, Blo
#define NSTAGE 3
#define GEMM_SMEM (NSTAGE*STAGEB)   // 184320 B

__device__ __forceinline__ void gemm_load_stage(
    uint32_t sbase, const __nv_bfloat16* __restrict__ Ahi,
    const __nv_bfloat16* __restrict__ Alo, const __nv_bfloat16* __restrict__ Bhi,
    const __nv_bfloat16* __restrict__ Blo, int bm, int bn, int k0, int K, int tid)
{
    const __nv_bfloat16* bases[4] = { Ahi, Alo, Bhi, Blo };
    const uint32_t offs[4] = { 0, ATSZ, 2*ATSZ, 2*ATSZ + BTSZ };
#pragma unroll
    for (int i = 0; i < 12; i++) {
        const int tile = (i < 4) ? 0 : (i < 8) ? 1 : (i < 10) ? 2 : 3;  // compile-time
        const int sub  = (tile < 2) ? (i & 3) : (i & 1);
        int f = sub * 256 + tid;              // A: 0..1023   B: 0..511
        int r  = f >> 2;                      // A row 0..255 / B row 0..127
        int cq = f & 3;                       // 16B chunk within 64B row
        int rowg = ((tile < 2) ? bm : bn) + r;
        const __nv_bfloat16* src = bases[tile] + (size_t)rowg * K + k0 + cq * 8;
        uint32_t dst = sbase + offs[tile] + r * (GPAD*2) + cq * 16;
        CP_ASYNC16(dst, src);
    }
}

template<int MODE>
__global__ __launch_bounds__(256, 1)
void gemm_mma(const __nv_bfloat16* __restrict__ Ahi, const __nv_bfloat16* __restrict__ Alo,
              const __nv_bfloat16* __restrict__ Bhi, const __nv_bfloat16* __restrict__ Blo,
              const float* __restrict__ bias, float* __restrict__ C,
              __nv_bfloat16* __restrict__ Chi, __nv_bfloat16* __restrict__ Clo,
              int N, int K)
{
    extern __shared__ char smem[];
    const uint32_t sb = smem_to_u32(smem);
    const int tid  = threadIdx.x;
    const int wid  = tid >> 5;
    const int lane = tid & 31;
    const int wm = wid >> 1;          // 0..3
    const int wn = wid & 1;           // 0..1
    const int bm = blockIdx.y * 256;
    const int bn = blockIdx.x * 128;

    float acc[4][8][4];
#pragma unroll
    for (int mi = 0; mi < 4; mi++)
#pragma unroll
        for (int ni = 0; ni < 8; ni++)
#pragma unroll
            for (int p = 0; p < 4; p++) acc[mi][ni][p] = 0.f;

    const int nchunks = K >> 5;

    gemm_load_stage(sb, Ahi, Alo, Bhi, Blo, bm, bn, 0, K, tid);
    CP_COMMIT;
    gemm_load_stage(sb + STAGEB, Ahi, Alo, Bhi, Blo, bm, bn, 32, K, tid);
    CP_COMMIT;

    const int arow = wm * 64 + (lane & 15);       // A row in 256-row tile
    const int acolh = (lane >> 4) * 8;
    const int brow = wn * 64 + (lane & 7);        // B row in 128-row tile
    const int bcolh = ((lane >> 3) & 1) * 8;

    for (int c = 0; c < nchunks; c++) {
        if (c + 1 < nchunks) { CP_WAIT1; } else { CP_WAIT0; }
        __syncthreads();
        if (c + 2 < nchunks) {
            int s2 = (c + 2) % NSTAGE;
            gemm_load_stage(sb + s2 * STAGEB, Ahi, Alo, Bhi, Blo, bm, bn,
                            (c + 2) << 5, K, tid);
            CP_COMMIT;
        }

        const uint32_t st = sb + (c % NSTAGE) * STAGEB;
        const uint32_t aHiB = st;
        const uint32_t aLoB = st + ATSZ;
        const uint32_t bHiB = st + 2*ATSZ;
        const uint32_t bLoB = st + 2*ATSZ + BTSZ;

#pragma unroll
        for (int kk = 0; kk < 32; kk += 16) {
            uint32_t ah[4][4], al[4][4];
#pragma unroll
            for (int mi = 0; mi < 4; mi++) {
                uint32_t off = (uint32_t)((arow + mi*16) * (GPAD*2) + (kk + acolh) * 2);
                ldsm_x4(aHiB + off, ah[mi][0], ah[mi][1], ah[mi][2], ah[mi][3]);
                ldsm_x4(aLoB + off, al[mi][0], al[mi][1], al[mi][2], al[mi][3]);
            }
#pragma unroll
            for (int ni = 0; ni < 8; ni++) {
                uint32_t off = (uint32_t)((brow + ni*8) * (GPAD*2) + (kk + bcolh) * 2);
                uint32_t bh[2], bl[2];
                ldsm_x2(bHiB + off, bh[0], bh[1]);
                ldsm_x2(bLoB + off, bl[0], bl[1]);
#pragma unroll
                for (int mi = 0; mi < 4; mi++) {
                    mma_bf16(acc[mi][ni], ah[mi], bh);
                    mma_bf16(acc[mi][ni], ah[mi], bl);
                    mma_bf16(acc[mi][ni], al[mi], bh);
                }
            }
        }
    }

    // epilogue
    const int qrow = lane >> 2;
    const int qcol = (lane & 3) * 2;
#pragma unroll
    for (int mi = 0; mi < 4; mi++) {
#pragma unroll
        for (int p = 0; p < 2; p++) {
            int row = bm + wm*64 + mi*16 + qrow + p*8;
#pragma unroll
            for (int ni = 0; ni < 8; ni++) {
                int col = bn + wn*64 + ni*8 + qcol;
                float v0 = acc[mi][ni][p*2 + 0];
                float v1 = acc[mi][ni][p*2 + 1];
                if (MODE >= 1) { v0 += bias[col]; v1 += bias[col+1]; }
                if (MODE == 2) {
                    v0 = gelu_exact(v0); v1 = gelu_exact(v1);
                    __nv_bfloat16 h0,l0,h1,l1;
                    split2(v0,h0,l0); split2(v1,h1,l1);
                    *(__nv_bfloat162*)&Chi[(size_t)row * N + col] = __nv_bfloat162(h0,h1);
                    *(__nv_bfloat162*)&Clo[(size_t)row * N + col] = __nv_bfloat162(l0,l1);
                } else {
                    float2 o; o.x = v0; o.y = v1;
                    *(float2*)&C[(size_t)row * N + col] = o;
                }
            }
        }
    }
}

// ---------------------------------------------------------------------------
// Attention: block = (32-query tile, h, b), 256 threads, fp32, reads fused qkv,
// writes output pre-split as bf16 hi/lo [M, D].
// ---------------------------------------------------------------------------
#define AT_QS   0            // [32][72]
#define AT_CH   2304         // [64][72]
#define AT_S    6912         // [32][257]
#define AT_RED  15136        // [32][8]
#define AT_RMAX 15392        // [32]
#define AT_RSUM 15424        // [32]
#define AT_MB   15456        // [256]
#define AT_TOTALF 15712
#define AT_SMEM_BYTES (AT_TOTALF*4)

__global__ __launch_bounds__(256)
void attn_kernel(const float* __restrict__ qkv, const int* __restrict__ mask,
                 __nv_bfloat16* __restrict__ ohi, __nv_bfloat16* __restrict__ olo)
{
    extern __shared__ float sm[];
    float* Qs   = sm + AT_QS;
    float* CH   = sm + AT_CH;
    float* S    = sm + AT_S;
    float* RED  = sm + AT_RED;
    float* RMAX = sm + AT_RMAX;
    float* RSUM = sm + AT_RSUM;
    float* MB   = sm + AT_MB;

    const int qt = blockIdx.x, h = blockIdx.y, b = blockIdx.z;
    const int tid = threadIdx.x;
    const int qq = tid >> 3;       // 0..31
    const int sub = tid & 7;       // 0..7
    const int rowbase = b * SS;
    const int q0 = qt * 32;
    const int hoff = h * DHD;

    MB[tid] = (1.0f - (float)mask[rowbase + tid]) * -10000.0f;

#pragma unroll
    for (int i = 0; i < 8; i++) {
        int f = tid + i * 256;
        int r = f >> 6, d = f & 63;
        Qs[r * 72 + d] = qkv[(size_t)(rowbase + q0 + r) * QKVN + hoff + d];
    }
    __syncthreads();

    // ---- scores (K at offset +DD in qkv) ----
    for (int kc = 0; kc < 4; kc++) {
#pragma unroll
        for (int i = 0; i < 16; i++) {
            int f = tid + i * 256;
            int r = f >> 6, d = f & 63;
            CH[r * 72 + d] = qkv[(size_t)(rowbase + kc * 64 + r) * QKVN + DD + hoff + d];
        }
        __syncthreads();
#pragma unroll
        for (int i = 0; i < 8; i++) {
            int j = sub + i * 8;
            float s = 0.f;
#pragma unroll
            for (int d = 0; d < 64; d += 4) {
                float4 qa = *(const float4*)&Qs[qq * 72 + d];
                float4 ka = *(const float4*)&CH[j * 72 + d];
                s += qa.x * ka.x + qa.y * ka.y + qa.z * ka.z + qa.w * ka.w;
            }
            S[qq * 257 + kc * 64 + j] = s * 0.125f + MB[kc * 64 + j];
        }
        __syncthreads();
    }

    // ---- softmax ----
    {
        float m = -3.4e38f;
#pragma unroll
        for (int i = 0; i < 32; i++) m = fmaxf(m, S[qq * 257 + sub + i * 8]);
        RED[qq * 8 + sub] = m;
        __syncthreads();
        if (sub == 0) {
            float mm = RED[qq * 8];
#pragma unroll
            for (int i = 1; i < 8; i++) mm = fmaxf(mm, RED[qq * 8 + i]);
            RMAX[qq] = mm;
        }
        __syncthreads();
        float mx = RMAX[qq];
        float ssum = 0.f;
#pragma unroll
        for (int i = 0; i < 32; i++) {
            int idx = qq * 257 + sub + i * 8;
            float e = __expf(S[idx] - mx);
            S[idx] = e;
            ssum += e;
        }
        RED[qq * 8 + sub] = ssum;
        __syncthreads();
        if (sub == 0) {
            float t = 0.f;
#pragma unroll
            for (int i = 0; i < 8; i++) t += RED[qq * 8 + i];
            RSUM[qq] = t;
        }
        __syncthreads();
    }

    // ---- O = P @ V  (V at offset +2*DD) ----
    float acc[8];
#pragma unroll
    for (int m2 = 0; m2 < 8; m2++) acc[m2] = 0.f;
    const int d0 = sub * 8;
    for (int vc = 0; vc < 4; vc++) {
        __syncthreads();
#pragma unroll
        for (int i = 0; i < 16; i++) {
            int f = tid + i * 256;
            int r = f >> 6, d = f & 63;
            CH[r * 72 + d] = qkv[(size_t)(rowbase + vc * 64 + r) * QKVN + 2*DD + hoff + d];
        }
        __syncthreads();
#pragma unroll 4
        for (int j = 0; j < 64; j++) {
            float p = S[qq * 257 + vc * 64 + j];
            float4 va = *(const float4*)&CH[j * 72 + d0];
            float4 vb = *(const float4*)&CH[j * 72 + d0 + 4];
            acc[0] += p * va.x; acc[1] += p * va.y;
            acc[2] += p * va.z; acc[3] += p * va.w;
            acc[4] += p * vb.x; acc[5] += p * vb.y;
            acc[6] += p * vb.z; acc[7] += p * vb.w;
        }
    }
    float inv = 1.0f / RSUM[qq];
    size_t obase = (size_t)(rowbase + q0 + qq) * DD + hoff + d0;
#pragma unroll
    for (int m2 = 0; m2 < 8; m2 += 2) {
        float y0 = acc[m2] * inv, y1 = acc[m2+1] * inv;
        __nv_bfloat16 h0,l0,h1,l1;
        split2(y0,h0,l0); split2(y1,h1,l1);
        *(__nv_bfloat162*)&ohi[obase + m2] = __nv_bfloat162(h0,h1);
        *(__nv_bfloat162*)&olo[obase + m2] = __nv_bfloat162(l0,l1);
    }
}

// ---------------------------------------------------------------------------
// sense key projection + final top-2
// ---------------------------------------------------------------------------
__global__ __launch_bounds__(64)
void sense_k_kernel(const float* __restrict__ sense, const float* __restrict__ Wk,
                    float* __restrict__ sk)
{
    int j = blockIdx.x, t = threadIdx.x;
    float s = 0.f;
    for (int d = 0; d < DD; d++)
        s += sense[(size_t)j*DD + d] * Wk[(size_t)d*NATT + t];
    sk[j*NATT + t] = s;
}

__global__ __launch_bounds__(64)
void final_kernel(const float* __restrict__ x, const int* __restrict__ loc,
                  const float* __restrict__ Wq, const float* __restrict__ sk,
                  float* __restrict__ out)
{
    int b = blockIdx.x, t = threadIdx.x;
    __shared__ float pun[DD];
    __shared__ float pq[NATT];
    __shared__ float sc[NSENSE];

    int r = b*SS + loc[b];
    for (int d = t; d < DD; d += 64) pun[d] = x[(size_t)r*DD + d];
    __syncthreads();

    float s = 0.f;
    for (int d = 0; d < DD; d++) s += pun[d] * Wq[(size_t)d*NATT + t];
    pq[t] = s;
    __syncthreads();

    float sv = 0.f;
#pragma unroll
    for (int u = 0; u < NATT; u++) sv += pq[u] * sk[t*NATT + u];
    sc[t] = sv * 0.125f;
    __syncthreads();

    if (t == 0) {
        int i1 = 0; float b1v = sc[0];
        for (int i = 1; i < NSENSE; i++) if (sc[i] > b1v) { b1v = sc[i]; i1 = i; }
        int i2 = -1; float b2v = -3.4e38f;
        for (int i = 0; i < NSENSE; i++) if (i != i1 && sc[i] > b2v) { b2v = sc[i]; i2 = i; }
        out[b*2+0] = (float)i1;
        out[b*2+1] = (float)i2;
    }
}

// ---------------------------------------------------------------------------
// launch
// ---------------------------------------------------------------------------
extern "C" void kernel_launch(void* const* d_in, const int* in_sizes, int n_in,
                              void* d_out, int out_size)
{
    const int*   input_ids = (const int*)  d_in[0];
    const int*   type_ids  = (const int*)  d_in[1];
    const int*   attn_mask = (const int*)  d_in[2];
    const int*   location  = (const int*)  d_in[3];
    const float* sense_emb = (const float*)d_in[4];
    const float* word_emb  = (const float*)d_in[5];
    const float* pos_emb   = (const float*)d_in[6];
    const float* type_emb  = (const float*)d_in[7];
    const float* emb_ln_g  = (const float*)d_in[8];
    const float* emb_ln_b  = (const float*)d_in[9];
    const float* Wq = (const float*)d_in[10];
    const float* bq = (const float*)d_in[11];
    const float* Wk = (const float*)d_in[12];
    const float* bk = (const float*)d_in[13];
    const float* Wv = (const float*)d_in[14];
    const float* bv = (const float*)d_in[15];
    const float* Wo = (const float*)d_in[16];
    const float* bo = (const float*)d_in[17];
    const float* ln1_g = (const float*)d_in[18];
    const float* ln1_b = (const float*)d_in[19];
    const float* W1 = (const float*)d_in[20];
    const float* b1 = (const float*)d_in[21];
    const float* W2 = (const float*)d_in[22];
    const float* b2 = (const float*)d_in[23];
    const float* ln2_g = (const float*)d_in[24];
    const float* ln2_b = (const float*)d_in[25];
    const float* att_Wq = (const float*)d_in[26];
    const float* att_Wk = (const float*)d_in[27];

    float *x, *qkv, *tmp, *sk, *cbias;
    __nv_bfloat16 *wthi, *wtlo, *ahi, *alo, *bhi, *blo;
    cudaGetSymbolAddress((void**)&x,     g_x);
    cudaGetSymbolAddress((void**)&qkv,   g_qkv);
    cudaGetSymbolAddress((void**)&tmp,   g_tmp);
    cudaGetSymbolAddress((void**)&sk,    g_sk);
    cudaGetSymbolAddress((void**)&cbias, g_cbias);
    cudaGetSymbolAddress((void**)&wthi,  g_wthi);
    cudaGetSymbolAddress((void**)&wtlo,  g_wtlo);
    cudaGetSymbolAddress((void**)&ahi,   g_ahi);
    cudaGetSymbolAddress((void**)&alo,   g_alo);
    cudaGetSymbolAddress((void**)&bhi,   g_bhi);
    cudaGetSymbolAddress((void**)&blo,   g_blo);

    cudaFuncSetAttribute(gemm_mma<0>, cudaFuncAttributeMaxDynamicSharedMemorySize, GEMM_SMEM);
    cudaFuncSetAttribute(gemm_mma<1>, cudaFuncAttributeMaxDynamicSharedMemorySize, GEMM_SMEM);
    cudaFuncSetAttribute(gemm_mma<2>, cudaFuncAttributeMaxDynamicSharedMemorySize, GEMM_SMEM);
    cudaFuncSetAttribute(attn_kernel, cudaFuncAttributeMaxDynamicSharedMemorySize, AT_SMEM_BYTES);

    // ---- weight prep ----
    dim3 tb(32, 8);
    for (int l = 0; l < LL; l++) {
        size_t base = (size_t)l * LWSTRIDE;
        const float* srcs[4] = { Wq + (size_t)l*DD*DD, Wk + (size_t)l*DD*DD,
                                 Wv + (size_t)l*DD*DD, Wo + (size_t)l*DD*DD };
        for (int m2 = 0; m2 < 4; m2++) {
            size_t off = base + (size_t)m2 * LW_QKVO;
            transpose_split_kernel<<<dim3(DD/32, DD/32), tb>>>(srcs[m2], wthi + off, wtlo + off, DD, DD);
        }
        transpose_split_kernel<<<dim3(FFD/32, DD/32), tb>>>(W1 + (size_t)l*DD*FFD,
            wthi + base + 4*LW_QKVO, wtlo + base + 4*LW_QKVO, DD, FFD);
        transpose_split_kernel<<<dim3(DD/32, FFD/32), tb>>>(W2 + (size_t)l*FFD*DD,
            wthi + base + 4*LW_QKVO + LW_FF, wtlo + base + 4*LW_QKVO + LW_FF, FFD, DD);
    }
    concat_bias_kernel<<<(LL*QKVN + 255)/256, 256>>>(bq, bk, bv, cbias);

    embed_ln_kernel<<<MM, 256>>>(input_ids, type_ids, word_emb, pos_emb,
                                 type_emb, emb_ln_g, emb_ln_b, x, ahi, alo);

    dim3 gQKV(QKVN/128, MM/256);  // (18, 32)
    dim3 gD(DD/128, MM/256);      // (6, 32)
    dim3 gF(FFD/128, MM/256);     // (24, 32)

    for (int l = 0; l < LL; l++) {
        size_t base = (size_t)l * LWSTRIDE;
        const __nv_bfloat16* wqkv_h = wthi + base;
        const __nv_bfloat16* wqkv_l = wtlo + base;
        const __nv_bfloat16* wo_h = wthi + base + 3*LW_QKVO;  const __nv_bfloat16* wo_l = wtlo + base + 3*LW_QKVO;
        const __nv_bfloat16* w1_h = wthi + base + 4*LW_QKVO;  const __nv_bfloat16* w1_l = wtlo + base + 4*LW_QKVO;
        const __nv_bfloat16* w2_h = wthi + base + 4*LW_QKVO + LW_FF;
        const __nv_bfloat16* w2_l = wtlo + base + 4*LW_QKVO + LW_FF;

        gemm_mma<1><<<gQKV, 256, GEMM_SMEM>>>(ahi, alo, wqkv_h, wqkv_l,
                                              cbias + l*QKVN, qkv, nullptr, nullptr, QKVN, DD);

        attn_kernel<<<dim3(SS/32, HH, BB), 256, AT_SMEM_BYTES>>>(qkv, attn_mask, ahi, alo);

        gemm_mma<0><<<gD, 256, GEMM_SMEM>>>(ahi, alo, wo_h, wo_l, nullptr, tmp,
                                            nullptr, nullptr, DD, DD);
        ln_res_kernel<<<MM, 256>>>(x, tmp, bo + l*DD, ln1_g + l*DD, ln1_b + l*DD, ahi, alo);

        gemm_mma<2><<<gF, 256, GEMM_SMEM>>>(ahi, alo, w1_h, w1_l, b1 + l*FFD,
                                            nullptr, bhi, blo, FFD, DD);
        gemm_mma<0><<<gD, 256, GEMM_SMEM>>>(bhi, blo, w2_h, w2_l, nullptr, tmp,
                                            nullptr, nullptr, DD, FFD);
        ln_res_kernel<<<MM, 256>>>(x, tmp, b2 + l*DD, ln2_g + l*DD, ln2_b + l*DD, ahi, alo);
    }

    sense_k_kernel<<<NSENSE, NATT>>>(sense_emb, att_Wk, sk);
    final_kernel<<<BB, 64>>>(x, location, att_Wq, sk, (float*)d_out);
}

// round 7
// speedup vs baseline: 1.2471x; 1.2471x over previous
#include <cuda_runtime.h>
#include <cuda_fp16.h>
#include <math.h>
#include <stdint.h>

// ---------------------------------------------------------------------------
// Problem constants
// ---------------------------------------------------------------------------
#define BB 32
#define SS 256
#define MM (BB*SS)        // 8192 rows
#define DD 768
#define HH 12
#define DHD 64
#define FFD 3072
#define LL 12
#define NSENSE 64
#define NATT 64
#define QKVN (3*DD)       // 2304

#define LW_QKVO ((size_t)DD*DD)
#define LW_FF   ((size_t)DD*FFD)
#define LWSTRIDE (4*LW_QKVO + 2*LW_FF)

// ---------------------------------------------------------------------------
// Scratch (static __device__ arrays; no runtime allocation allowed)
// ---------------------------------------------------------------------------
__device__ float g_x  [(size_t)MM*DD];         // residual stream (fp32)
__device__ float g_qkv[(size_t)MM*QKVN];       // fused QKV output (fp32)
__device__ float g_tmp[(size_t)MM*DD];         // gemm output before LN
__device__ float g_sk [NSENSE*NATT];
__device__ float g_cbias[LL*QKVN];             // concatenated qkv bias

__device__ __half g_w16 [LL*LWSTRIDE];         // transposed weights [N,K] fp16
__device__ __half g_ahi [(size_t)MM*DD];       // activation hi (fp16)
__device__ __half g_alo [(size_t)MM*DD];       // activation lo (fp16)
__device__ __half g_bhi [(size_t)MM*FFD];      // ffn hidden hi
__device__ __half g_blo [(size_t)MM*FFD];      // ffn hidden lo

// ---------------------------------------------------------------------------
// asm helpers (sm_80-era features, legal on compute_103)
// ---------------------------------------------------------------------------
__device__ __forceinline__ uint32_t smem_to_u32(const void* smem_ptr) {
    uint32_t addr;
    asm("{ .reg .u64 tmp; cvta.to.shared.u64 tmp, %1; cvt.u32.u64 %0, tmp; }"
        : "=r"(addr) : "l"(smem_ptr));
    return addr;
}
#define CP_ASYNC16(dst_u32, src_ptr) \
    asm volatile("cp.async.cg.shared.global [%0], [%1], 16;" \
        :: "r"(dst_u32), "l"(src_ptr))
#define CP_COMMIT asm volatile("cp.async.commit_group;" ::: "memory")
#define CP_WAIT0  asm volatile("cp.async.wait_group 0;" ::: "memory")
#define CP_WAIT1  asm volatile("cp.async.wait_group 1;" ::: "memory")

__device__ __forceinline__ void ldsm_x4(uint32_t addr, uint32_t& r0, uint32_t& r1,
                                        uint32_t& r2, uint32_t& r3) {
    asm volatile("ldmatrix.sync.aligned.m8n8.x4.shared.b16 {%0,%1,%2,%3}, [%4];"
        : "=r"(r0), "=r"(r1), "=r"(r2), "=r"(r3) : "r"(addr));
}
__device__ __forceinline__ void ldsm_x2(uint32_t addr, uint32_t& r0, uint32_t& r1) {
    asm volatile("ldmatrix.sync.aligned.m8n8.x2.shared.b16 {%0,%1}, [%2];"
        : "=r"(r0), "=r"(r1) : "r"(addr));
}
__device__ __forceinline__ void mma_f16(float* c, const uint32_t* a, const uint32_t* b) {
    asm volatile(
        "mma.sync.aligned.m16n8k16.row.col.f32.f16.f16.f32 "
        "{%0,%1,%2,%3}, {%4,%5,%6,%7}, {%8,%9}, {%0,%1,%2,%3};"
        : "+f"(c[0]), "+f"(c[1]), "+f"(c[2]), "+f"(c[3])
        : "r"(a[0]), "r"(a[1]), "r"(a[2]), "r"(a[3]), "r"(b[0]), "r"(b[1]));
}

__device__ __forceinline__ void split2h(float f, __half& h, __half& l) {
    h = __float2half_rn(f);
    l = __float2half_rn(f - __half2float(h));
}

// ---------------------------------------------------------------------------
// weight prep: transpose [K,N] fp32 -> [N,K] fp16 (single rounding)
// ---------------------------------------------------------------------------
__global__ __launch_bounds__(256)
void transpose_h_kernel(const float* __restrict__ src,
                        __half* __restrict__ dst, int K, int N)
{
    __shared__ float t[32][33];
    int tx = threadIdx.x, ty = threadIdx.y;   // block (32,8)
    int nx = blockIdx.x*32 + tx;
    int ky = blockIdx.y*32;
#pragma unroll
    for (int i = 0; i < 4; i++)
        t[ty + i*8][tx] = src[(size_t)(ky + ty + i*8)*N + nx];
    __syncthreads();
    int kx = blockIdx.y*32 + tx;
    int ny = blockIdx.x*32;
#pragma unroll
    for (int i = 0; i < 4; i++)
        dst[(size_t)(ny + ty + i*8)*K + kx] = __float2half_rn(t[tx][ty + i*8]);
}

__global__ __launch_bounds__(256)
void concat_bias_kernel(const float* __restrict__ bq, const float* __restrict__ bk,
                        const float* __restrict__ bv, float* __restrict__ cb)
{
    int idx = blockIdx.x * 256 + threadIdx.x;
    if (idx >= LL * QKVN) return;
    int l = idx / QKVN, j = idx % QKVN;
    float v;
    if (j < DD)            v = bq[l*DD + j];
    else if (j < 2*DD)     v = bk[l*DD + j - DD];
    else                   v = bv[l*DD + j - 2*DD];
    cb[idx] = v;
}

// ---------------------------------------------------------------------------
// Embedding + LayerNorm -> x fp32 + (hi,lo) fp16 split
// ---------------------------------------------------------------------------
__global__ __launch_bounds__(256)
void embed_ln_kernel(const int* __restrict__ ids, const int* __restrict__ tt,
                     const float* __restrict__ we, const float* __restrict__ pe,
                     const float* __restrict__ te, const float* __restrict__ lg,
                     const float* __restrict__ lb, float* __restrict__ x,
                     __half* __restrict__ xhi, __half* __restrict__ xlo)
{
    int row = blockIdx.x;
    int s   = row % SS;
    int id  = ids[row];
    int t   = tt[row];
    int tid = threadIdx.x;
    const float* wr = we + (size_t)id * DD;
    const float* pr = pe + (size_t)s  * DD;
    const float* tr = te + (size_t)t  * DD;
    float v[3]; float sum = 0.f, sq = 0.f;
#pragma unroll
    for (int i = 0; i < 3; i++) {
        int d = tid + i * 256;
        float y = wr[d] + pr[d] + tr[d];
        v[i] = y; sum += y; sq += y * y;
    }
    __shared__ float sh1[256], sh2[256];
    sh1[tid] = sum; sh2[tid] = sq;
    __syncthreads();
    for (int st = 128; st > 0; st >>= 1) {
        if (tid < st) { sh1[tid] += sh1[tid+st]; sh2[tid] += sh2[tid+st]; }
        __syncthreads();
    }
    float mu  = sh1[0] * (1.f/768.f);
    float var = fmaxf(sh2[0] * (1.f/768.f) - mu*mu, 0.f);
    float inv = rsqrtf(var + 1e-12f);
#pragma unroll
    for (int i = 0; i < 3; i++) {
        int d = tid + i * 256;
        float y = (v[i]-mu)*inv*lg[d] + lb[d];
        size_t o = (size_t)row*DD + d;
        x[o] = y;
        __half h, l; split2h(y, h, l);
        xhi[o] = h; xlo[o] = l;
    }
}

// ---------------------------------------------------------------------------
// Residual + bias + LayerNorm -> x fp32 (in place) + fp16 split
// ---------------------------------------------------------------------------
__global__ __launch_bounds__(256)
void ln_res_kernel(float* __restrict__ x, const float* __restrict__ val,
                   const float* __restrict__ bias, const float* __restrict__ lg,
                   const float* __restrict__ lb,
                   __half* __restrict__ xhi, __half* __restrict__ xlo)
{
    int row = blockIdx.x;
    int tid = threadIdx.x;
    float v[3]; float sum = 0.f, sq = 0.f;
#pragma unroll
    for (int i = 0; i < 3; i++) {
        int d = tid + i * 256;
        float y = x[(size_t)row*DD + d] + val[(size_t)row*DD + d] + bias[d];
        v[i] = y; sum += y; sq += y * y;
    }
    __shared__ float sh1[256], sh2[256];
    sh1[tid] = sum; sh2[tid] = sq;
    __syncthreads();
    for (int st = 128; st > 0; st >>= 1) {
        if (tid < st) { sh1[tid] += sh1[tid+st]; sh2[tid] += sh2[tid+st]; }
        __syncthreads();
    }
    float mu  = sh1[0] * (1.f/768.f);
    float var = fmaxf(sh2[0] * (1.f/768.f) - mu*mu, 0.f);
    float inv = rsqrtf(var + 1e-12f);
#pragma unroll
    for (int i = 0; i < 3; i++) {
        int d = tid + i * 256;
        float y = (v[i]-mu)*inv*lg[d] + lb[d];
        size_t o = (size_t)row*DD + d;
        x[o] = y;
        __half h, l; split2h(y, h, l);
        xhi[o] = h; xlo[o] = l;
    }
}

// ---------------------------------------------------------------------------
// HMMA GEMM: C[M,N] = A[M,K] @ Wt[N,K]^T.
// A split (fp16 hi+lo), W rounded to fp16 once -> 2 mma terms.
// CTA tile 128x128x32, 8 warps (2m x 4n), mma m16n8k16, 3-stage cp.async.
// MODE 0: C fp32   MODE 1: C fp32 + bias   MODE 2: bias+gelu -> fp16 split out
// ---------------------------------------------------------------------------
__device__ __forceinline__ float gelu_exact(float x) {
    return 0.5f * x * (1.0f + erff(x * 0.70710678118654752f));
}

#define GPAD 40                  // smem row stride (elements) -> 80 bytes
#define TSZB (128*GPAD*2)        // 10240 B per 128x32 fp16 tile
#define STAGEB (3*TSZB)          // Ahi, Alo, W  (30720 B)
#define NSTAGE 3
#define GEMM_SMEM (NSTAGE*STAGEB)   // 92160 B

__device__ __forceinline__ void gemm_load_stage(
    uint32_t sbase, const __half* __restrict__ Ahi, const __half* __restrict__ Alo,
    const __half* __restrict__ W, int bm, int bn, int k0, int K, int tid)
{
    const __half* bases[3] = { Ahi, Alo, W };
#pragma unroll
    for (int i = 0; i < 6; i++) {
        const int tile = i >> 1;                 // 0..2 (compile-time)
        int f = ((i & 1) << 8) + tid;            // 0..511
        int r  = f >> 2;                         // 0..127
        int cq = f & 3;                          // 16B chunk
        int rowg = ((tile < 2) ? bm : bn) + r;
        const __half* src = bases[tile] + (size_t)rowg * K + k0 + cq * 8;
        uint32_t dst = sbase + tile * TSZB + r * (GPAD*2) + cq * 16;
        CP_ASYNC16(dst, src);
    }
}

template<int MODE>
__global__ __launch_bounds__(256)
void gemm_mma(const __half* __restrict__ Ahi, const __half* __restrict__ Alo,
              const __half* __restrict__ W, const float* __restrict__ bias,
              float* __restrict__ C, __half* __restrict__ Chi, __half* __restrict__ Clo,
              int N, int K)
{
    extern __shared__ char smem[];
    const uint32_t sb = smem_to_u32(smem);
    const int tid  = threadIdx.x;
    const int wid  = tid >> 5;
    const int lane = tid & 31;
    const int wm = wid >> 2;          // 0..1
    const int wn = wid & 3;           // 0..3
    const int bm = blockIdx.y * 128;
    const int bn = blockIdx.x * 128;

    float acc[4][4][4];
#pragma unroll
    for (int mi = 0; mi < 4; mi++)
#pragma unroll
        for (int ni = 0; ni < 4; ni++)
#pragma unroll
            for (int p = 0; p < 4; p++) acc[mi][ni][p] = 0.f;

    const int nchunks = K >> 5;

    gemm_load_stage(sb, Ahi, Alo, W, bm, bn, 0, K, tid);
    CP_COMMIT;
    gemm_load_stage(sb + STAGEB, Ahi, Alo, W, bm, bn, 32, K, tid);
    CP_COMMIT;

    const int arow = wm * 64 + (lane & 15);
    const int acolh = (lane >> 4) * 8;
    const int brow = wn * 32 + (lane & 7);
    const int bcolh = ((lane >> 3) & 1) * 8;

    for (int c = 0; c < nchunks; c++) {
        if (c + 1 < nchunks) { CP_WAIT1; } else { CP_WAIT0; }
        __syncthreads();
        if (c + 2 < nchunks) {
            int s2 = (c + 2) % NSTAGE;
            gemm_load_stage(sb + s2 * STAGEB, Ahi, Alo, W, bm, bn,
                            (c + 2) << 5, K, tid);
            CP_COMMIT;
        }

        const uint32_t st = sb + (c % NSTAGE) * STAGEB;
        const uint32_t aHiB = st;
        const uint32_t aLoB = st + TSZB;
        const uint32_t wB   = st + 2*TSZB;

#pragma unroll
        for (int kk = 0; kk < 32; kk += 16) {
            uint32_t ah[4][4], al[4][4];
#pragma unroll
            for (int mi = 0; mi < 4; mi++) {
                uint32_t off = (uint32_t)((arow + mi*16) * (GPAD*2) + (kk + acolh) * 2);
                ldsm_x4(aHiB + off, ah[mi][0], ah[mi][1], ah[mi][2], ah[mi][3]);
                ldsm_x4(aLoB + off, al[mi][0], al[mi][1], al[mi][2], al[mi][3]);
            }
#pragma unroll
            for (int ni = 0; ni < 4; ni++) {
                uint32_t off = (uint32_t)((brow + ni*8) * (GPAD*2) + (kk + bcolh) * 2);
                uint32_t bw[2];
                ldsm_x2(wB + off, bw[0], bw[1]);
#pragma unroll
                for (int mi = 0; mi < 4; mi++) {
                    mma_f16(acc[mi][ni], ah[mi], bw);
                    mma_f16(acc[mi][ni], al[mi], bw);
                }
            }
        }
    }

    // epilogue
    const int qrow = lane >> 2;
    const int qcol = (lane & 3) * 2;
#pragma unroll
    for (int mi = 0; mi < 4; mi++) {
#pragma unroll
        for (int p = 0; p < 2; p++) {
            int row = bm + wm*64 + mi*16 + qrow + p*8;
#pragma unroll
            for (int ni = 0; ni < 4; ni++) {
                int col = bn + wn*32 + ni*8 + qcol;
                float v0 = acc[mi][ni][p*2 + 0];
                float v1 = acc[mi][ni][p*2 + 1];
                if (MODE >= 1) { v0 += bias[col]; v1 += bias[col+1]; }
                if (MODE == 2) {
                    v0 = gelu_exact(v0); v1 = gelu_exact(v1);
                    __half h0,l0,h1,l1;
                    split2h(v0,h0,l0); split2h(v1,h1,l1);
                    *(__half2*)&Chi[(size_t)row * N + col] = __halves2half2(h0,h1);
                    *(__half2*)&Clo[(size_t)row * N + col] = __halves2half2(l0,l1);
                } else {
                    float2 o; o.x = v0; o.y = v1;
                    *(float2*)&C[(size_t)row * N + col] = o;
                }
            }
        }
    }
}

// ---------------------------------------------------------------------------
// Attention: block = (32-query tile, h, b), 256 threads, fp32, reads fused qkv,
// writes output pre-split as fp16 hi/lo [M, D].
// ---------------------------------------------------------------------------
#define AT_QS   0            // [32][72]
#define AT_CH   2304         // [64][72]
#define AT_S    6912         // [32][257]
#define AT_RED  15136        // [32][8]
#define AT_RMAX 15392        // [32]
#define AT_RSUM 15424        // [32]
#define AT_MB   15456        // [256]
#define AT_TOTALF 15712
#define AT_SMEM_BYTES (AT_TOTALF*4)

__global__ __launch_bounds__(256)
void attn_kernel(const float* __restrict__ qkv, const int* __restrict__ mask,
                 __half* __restrict__ ohi, __half* __restrict__ olo)
{
    extern __shared__ float sm[];
    float* Qs   = sm + AT_QS;
    float* CH   = sm + AT_CH;
    float* S    = sm + AT_S;
    float* RED  = sm + AT_RED;
    float* RMAX = sm + AT_RMAX;
    float* RSUM = sm + AT_RSUM;
    float* MB   = sm + AT_MB;

    const int qt = blockIdx.x, h = blockIdx.y, b = blockIdx.z;
    const int tid = threadIdx.x;
    const int qq = tid >> 3;       // 0..31
    const int sub = tid & 7;       // 0..7
    const int rowbase = b * SS;
    const int q0 = qt * 32;
    const int hoff = h * DHD;

    MB[tid] = (1.0f - (float)mask[rowbase + tid]) * -10000.0f;

#pragma unroll
    for (int i = 0; i < 8; i++) {
        int f = tid + i * 256;
        int r = f >> 6, d = f & 63;
        Qs[r * 72 + d] = qkv[(size_t)(rowbase + q0 + r) * QKVN + hoff + d];
    }
    __syncthreads();

    // ---- scores (K at offset +DD) ----
    for (int kc = 0; kc < 4; kc++) {
#pragma unroll
        for (int i = 0; i < 16; i++) {
            int f = tid + i * 256;
            int r = f >> 6, d = f & 63;
            CH[r * 72 + d] = qkv[(size_t)(rowbase + kc * 64 + r) * QKVN + DD + hoff + d];
        }
        __syncthreads();
#pragma unroll
        for (int i = 0; i < 8; i++) {
            int j = sub + i * 8;
            float s = 0.f;
#pragma unroll
            for (int d = 0; d < 64; d += 4) {
                float4 qa = *(const float4*)&Qs[qq * 72 + d];
                float4 ka = *(const float4*)&CH[j * 72 + d];
                s += qa.x * ka.x + qa.y * ka.y + qa.z * ka.z + qa.w * ka.w;
            }
            S[qq * 257 + kc * 64 + j] = s * 0.125f + MB[kc * 64 + j];
        }
        __syncthreads();
    }

    // ---- softmax ----
    {
        float m = -3.4e38f;
#pragma unroll
        for (int i = 0; i < 32; i++) m = fmaxf(m, S[qq * 257 + sub + i * 8]);
        RED[qq * 8 + sub] = m;
        __syncthreads();
        if (sub == 0) {
            float mm = RED[qq * 8];
#pragma unroll
            for (int i = 1; i < 8; i++) mm = fmaxf(mm, RED[qq * 8 + i]);
            RMAX[qq] = mm;
        }
        __syncthreads();
        float mx = RMAX[qq];
        float ssum = 0.f;
#pragma unroll
        for (int i = 0; i < 32; i++) {
            int idx = qq * 257 + sub + i * 8;
            float e = __expf(S[idx] - mx);
            S[idx] = e;
            ssum += e;
        }
        RED[qq * 8 + sub] = ssum;
        __syncthreads();
        if (sub == 0) {
            float t = 0.f;
#pragma unroll
            for (int i = 0; i < 8; i++) t += RED[qq * 8 + i];
            RSUM[qq] = t;
        }
        __syncthreads();
    }

    // ---- O = P @ V  (V at offset +2*DD) ----
    float acc[8];
#pragma unroll
    for (int m2 = 0; m2 < 8; m2++) acc[m2] = 0.f;
    const int d0 = sub * 8;
    for (int vc = 0; vc < 4; vc++) {
        __syncthreads();
#pragma unroll
        for (int i = 0; i < 16; i++) {
            int f = tid + i * 256;
            int r = f >> 6, d = f & 63;
            CH[r * 72 + d] = qkv[(size_t)(rowbase + vc * 64 + r) * QKVN + 2*DD + hoff + d];
        }
        __syncthreads();
#pragma unroll 4
        for (int j = 0; j < 64; j++) {
            float p = S[qq * 257 + vc * 64 + j];
            float4 va = *(const float4*)&CH[j * 72 + d0];
            float4 vb = *(const float4*)&CH[j * 72 + d0 + 4];
            acc[0] += p * va.x; acc[1] += p * va.y;
            acc[2] += p * va.z; acc[3] += p * va.w;
            acc[4] += p * vb.x; acc[5] += p * vb.y;
            acc[6] += p * vb.z; acc[7] += p * vb.w;
        }
    }
    float inv = 1.0f / RSUM[qq];
    size_t obase = (size_t)(rowbase + q0 + qq) * DD + hoff + d0;
#pragma unroll
    for (int m2 = 0; m2 < 8; m2 += 2) {
        float y0 = acc[m2] * inv, y1 = acc[m2+1] * inv;
        __half h0,l0,h1,l1;
        split2h(y0,h0,l0); split2h(y1,h1,l1);
        *(__half2*)&ohi[obase + m2] = __halves2half2(h0,h1);
        *(__half2*)&olo[obase + m2] = __halves2half2(l0,l1);
    }
}

// ---------------------------------------------------------------------------
// sense key projection + final top-2
// ---------------------------------------------------------------------------
__global__ __launch_bounds__(64)
void sense_k_kernel(const float* __restrict__ sense, const float* __restrict__ Wk,
                    float* __restrict__ sk)
{
    int j = blockIdx.x, t = threadIdx.x;
    float s = 0.f;
    for (int d = 0; d < DD; d++)
        s += sense[(size_t)j*DD + d] * Wk[(size_t)d*NATT + t];
    sk[j*NATT + t] = s;
}

__global__ __launch_bounds__(64)
void final_kernel(const float* __restrict__ x, const int* __restrict__ loc,
                  const float* __restrict__ Wq, const float* __restrict__ sk,
                  float* __restrict__ out)
{
    int b = blockIdx.x, t = threadIdx.x;
    __shared__ float pun[DD];
    __shared__ float pq[NATT];
    __shared__ float sc[NSENSE];

    int r = b*SS + loc[b];
    for (int d = t; d < DD; d += 64) pun[d] = x[(size_t)r*DD + d];
    __syncthreads();

    float s = 0.f;
    for (int d = 0; d < DD; d++) s += pun[d] * Wq[(size_t)d*NATT + t];
    pq[t] = s;
    __syncthreads();

    float sv = 0.f;
#pragma unroll
    for (int u = 0; u < NATT; u++) sv += pq[u] * sk[t*NATT + u];
    sc[t] = sv * 0.125f;
    __syncthreads();

    if (t == 0) {
        int i1 = 0; float b1v = sc[0];
        for (int i = 1; i < NSENSE; i++) if (sc[i] > b1v) { b1v = sc[i]; i1 = i; }
        int i2 = -1; float b2v = -3.4e38f;
        for (int i = 0; i < NSENSE; i++) if (i != i1 && sc[i] > b2v) { b2v = sc[i]; i2 = i; }
        out[b*2+0] = (float)i1;
        out[b*2+1] = (float)i2;
    }
}

// ---------------------------------------------------------------------------
// launch
// ---------------------------------------------------------------------------
extern "C" void kernel_launch(void* const* d_in, const int* in_sizes, int n_in,
                              void* d_out, int out_size)
{
    const int*   input_ids = (const int*)  d_in[0];
    const int*   type_ids  = (const int*)  d_in[1];
    const int*   attn_mask = (const int*)  d_in[2];
    const int*   location  = (const int*)  d_in[3];
    const float* sense_emb = (const float*)d_in[4];
    const float* word_emb  = (const float*)d_in[5];
    const float* pos_emb   = (const float*)d_in[6];
    const float* type_emb  = (const float*)d_in[7];
    const float* emb_ln_g  = (const float*)d_in[8];
    const float* emb_ln_b  = (const float*)d_in[9];
    const float* Wq = (const float*)d_in[10];
    const float* bq = (const float*)d_in[11];
    const float* Wk = (const float*)d_in[12];
    const float* bk = (const float*)d_in[13];
    const float* Wv = (const float*)d_in[14];
    const float* bv = (const float*)d_in[15];
    const float* Wo = (const float*)d_in[16];
    const float* bo = (const float*)d_in[17];
    const float* ln1_g = (const float*)d_in[18];
    const float* ln1_b = (const float*)d_in[19];
    const float* W1 = (const float*)d_in[20];
    const float* b1 = (const float*)d_in[21];
    const float* W2 = (const float*)d_in[22];
    const float* b2 = (const float*)d_in[23];
    const float* ln2_g = (const float*)d_in[24];
    const float* ln2_b = (const float*)d_in[25];
    const float* att_Wq = (const float*)d_in[26];
    const float* att_Wk = (const float*)d_in[27];

    float *x, *qkv, *tmp, *sk, *cbias;
    __half *w16, *ahi, *alo, *bhi, *blo;
    cudaGetSymbolAddress((void**)&x,     g_x);
    cudaGetSymbolAddress((void**)&qkv,   g_qkv);
    cudaGetSymbolAddress((void**)&tmp,   g_tmp);
    cudaGetSymbolAddress((void**)&sk,    g_sk);
    cudaGetSymbolAddress((void**)&cbias, g_cbias);
    cudaGetSymbolAddress((void**)&w16,   g_w16);
    cudaGetSymbolAddress((void**)&ahi,   g_ahi);
    cudaGetSymbolAddress((void**)&alo,   g_alo);
    cudaGetSymbolAddress((void**)&bhi,   g_bhi);
    cudaGetSymbolAddress((void**)&blo,   g_blo);

    cudaFuncSetAttribute(gemm_mma<0>, cudaFuncAttributeMaxDynamicSharedMemorySize, GEMM_SMEM);
    cudaFuncSetAttribute(gemm_mma<1>, cudaFuncAttributeMaxDynamicSharedMemorySize, GEMM_SMEM);
    cudaFuncSetAttribute(gemm_mma<2>, cudaFuncAttributeMaxDynamicSharedMemorySize, GEMM_SMEM);
    cudaFuncSetAttribute(attn_kernel, cudaFuncAttributeMaxDynamicSharedMemorySize, AT_SMEM_BYTES);

    // ---- weight prep (single fp16 copy) ----
    dim3 tb(32, 8);
    for (int l = 0; l < LL; l++) {
        size_t base = (size_t)l * LWSTRIDE;
        const float* srcs[4] = { Wq + (size_t)l*DD*DD, Wk + (size_t)l*DD*DD,
                                 Wv + (size_t)l*DD*DD, Wo + (size_t)l*DD*DD };
        for (int m2 = 0; m2 < 4; m2++)
            transpose_h_kernel<<<dim3(DD/32, DD/32), tb>>>(srcs[m2],
                w16 + base + (size_t)m2 * LW_QKVO, DD, DD);
        transpose_h_kernel<<<dim3(FFD/32, DD/32), tb>>>(W1 + (size_t)l*DD*FFD,
            w16 + base + 4*LW_QKVO, DD, FFD);
        transpose_h_kernel<<<dim3(DD/32, FFD/32), tb>>>(W2 + (size_t)l*FFD*DD,
            w16 + base + 4*LW_QKVO + LW_FF, FFD, DD);
    }
    concat_bias_kernel<<<(LL*QKVN + 255)/256, 256>>>(bq, bk, bv, cbias);

    embed_ln_kernel<<<MM, 256>>>(input_ids, type_ids, word_emb, pos_emb,
                                 type_emb, emb_ln_g, emb_ln_b, x, ahi, alo);

    dim3 gQKV(QKVN/128, MM/128);  // (18, 64)
    dim3 gD(DD/128, MM/128);      // (6, 64)
    dim3 gF(FFD/128, MM/128);     // (24, 64)

    for (int l = 0; l < LL; l++) {
        size_t base = (size_t)l * LWSTRIDE;
        const __half* wqkv = w16 + base;                       // [2304,768]
        const __half* wo   = w16 + base + 3*LW_QKVO;           // [768,768]
        const __half* w1   = w16 + base + 4*LW_QKVO;           // [3072,768]
        const __half* w2   = w16 + base + 4*LW_QKVO + LW_FF;   // [768,3072]

        gemm_mma<1><<<gQKV, 256, GEMM_SMEM>>>(ahi, alo, wqkv, cbias + l*QKVN,
                                              qkv, nullptr, nullptr, QKVN, DD);

        attn_kernel<<<dim3(SS/32, HH, BB), 256, AT_SMEM_BYTES>>>(qkv, attn_mask, ahi, alo);

        gemm_mma<0><<<gD, 256, GEMM_SMEM>>>(ahi, alo, wo, nullptr, tmp,
                                            nullptr, nullptr, DD, DD);
        ln_res_kernel<<<MM, 256>>>(x, tmp, bo + l*DD, ln1_g + l*DD, ln1_b + l*DD, ahi, alo);

        gemm_mma<2><<<gF, 256, GEMM_SMEM>>>(ahi, alo, w1, b1 + l*FFD,
                                            nullptr, bhi, blo, FFD, DD);
        gemm_mma<0><<<gD, 256, GEMM_SMEM>>>(bhi, blo, w2, nullptr, tmp,
                                            nullptr, nullptr, DD, FFD);
        ln_res_kernel<<<MM, 256>>>(x, tmp, b2 + l*DD, ln2_g + l*DD, ln2_b + l*DD, ahi, alo);
    }

    sense_k_kernel<<<NSENSE, NATT>>>(sense_emb, att_Wk, sk);
    final_kernel<<<BB, 64>>>(x, location, att_Wq, sk, (float*)d_out);
}

// round 8
// speedup vs baseline: 1.2992x; 1.0417x over previous
#include <cuda_runtime.h>
#include <cuda_fp16.h>
#include <math.h>
#include <stdint.h>

// ---------------------------------------------------------------------------
// Problem constants
// ---------------------------------------------------------------------------
#define BB 32
#define SS 256
#define MM (BB*SS)        // 8192 rows
#define DD 768
#define HH 12
#define DHD 64
#define FFD 3072
#define LL 12
#define NSENSE 64
#define NATT 64
#define QKVN (3*DD)       // 2304

#define LW_QKVO ((size_t)DD*DD)
#define LW_FF   ((size_t)DD*FFD)
#define LWSTRIDE (4*LW_QKVO + 2*LW_FF)

// ---------------------------------------------------------------------------
// Scratch (static __device__ arrays; no runtime allocation allowed)
// ---------------------------------------------------------------------------
__device__ float  g_x  [(size_t)MM*DD];        // residual stream (fp32)
__device__ __half g_qkv[(size_t)MM*QKVN];      // fused QKV output (fp16)
__device__ float  g_tmp[(size_t)MM*DD];        // gemm output before LN
__device__ float  g_sk [NSENSE*NATT];
__device__ float  g_cbias[LL*QKVN];            // concatenated qkv bias

__device__ __half g_w16 [LL*LWSTRIDE];         // transposed weights [N,K] fp16
__device__ __half g_ahi [(size_t)MM*DD];       // activation hi (fp16)
__device__ __half g_alo [(size_t)MM*DD];       // activation lo (fp16)
__device__ __half g_bhi [(size_t)MM*FFD];      // ffn hidden hi
__device__ __half g_blo [(size_t)MM*FFD];      // ffn hidden lo

// ---------------------------------------------------------------------------
// asm helpers (sm_80-era features, legal on compute_103)
// ---------------------------------------------------------------------------
__device__ __forceinline__ uint32_t smem_to_u32(const void* smem_ptr) {
    uint32_t addr;
    asm("{ .reg .u64 tmp; cvta.to.shared.u64 tmp, %1; cvt.u32.u64 %0, tmp; }"
        : "=r"(addr) : "l"(smem_ptr));
    return addr;
}
#define CP_ASYNC16(dst_u32, src_ptr) \
    asm volatile("cp.async.cg.shared.global [%0], [%1], 16;" \
        :: "r"(dst_u32), "l"(src_ptr))
#define CP_COMMIT asm volatile("cp.async.commit_group;" ::: "memory")
#define CP_WAIT0  asm volatile("cp.async.wait_group 0;" ::: "memory")
#define CP_WAIT1  asm volatile("cp.async.wait_group 1;" ::: "memory")

__device__ __forceinline__ void ldsm_x4(uint32_t addr, uint32_t& r0, uint32_t& r1,
                                        uint32_t& r2, uint32_t& r3) {
    asm volatile("ldmatrix.sync.aligned.m8n8.x4.shared.b16 {%0,%1,%2,%3}, [%4];"
        : "=r"(r0), "=r"(r1), "=r"(r2), "=r"(r3) : "r"(addr));
}
__device__ __forceinline__ void ldsm_x2(uint32_t addr, uint32_t& r0, uint32_t& r1) {
    asm volatile("ldmatrix.sync.aligned.m8n8.x2.shared.b16 {%0,%1}, [%2];"
        : "=r"(r0), "=r"(r1) : "r"(addr));
}
__device__ __forceinline__ void mma_f16(float* c, const uint32_t* a, const uint32_t* b) {
    asm volatile(
        "mma.sync.aligned.m16n8k16.row.col.f32.f16.f16.f32 "
        "{%0,%1,%2,%3}, {%4,%5,%6,%7}, {%8,%9}, {%0,%1,%2,%3};"
        : "+f"(c[0]), "+f"(c[1]), "+f"(c[2]), "+f"(c[3])
        : "r"(a[0]), "r"(a[1]), "r"(a[2]), "r"(a[3]), "r"(b[0]), "r"(b[1]));
}

__device__ __forceinline__ void split2h(float f, __half& h, __half& l) {
    h = __float2half_rn(f);
    l = __float2half_rn(f - __half2float(h));
}

// ---------------------------------------------------------------------------
// weight prep: ALL transposes in ONE launch.
// Per layer: 4x [768,768] (576 tiles each), W1 [768,3072] (96x24=2304 tiles),
// W2 [3072,768] (24x96=2304 tiles). 6912 tiles/layer, 82944 total.
// ---------------------------------------------------------------------------
#define TILES_PER_LAYER 6912

__global__ __launch_bounds__(256)
void transpose_all_kernel(const float* __restrict__ Wq, const float* __restrict__ Wk,
                          const float* __restrict__ Wv, const float* __restrict__ Wo,
                          const float* __restrict__ W1, const float* __restrict__ W2,
                          __half* __restrict__ w16)
{
    __shared__ float t[32][33];
    int bid = blockIdx.x;
    int l = bid / TILES_PER_LAYER;
    int r = bid % TILES_PER_LAYER;

    const float* src;
    __half* dst;
    int K, N, tilex, tiley;
    size_t base = (size_t)l * LWSTRIDE;

    if (r < 2304) {
        int m = r / 576;                     // 0..3 (Wq,Wk,Wv,Wo)
        int tile = r % 576;
        const float* srcs0 = (m == 0) ? Wq : (m == 1) ? Wk : (m == 2) ? Wv : Wo;
        src = srcs0 + (size_t)l * DD * DD;
        dst = w16 + base + (size_t)m * LW_QKVO;
        K = DD; N = DD;
        tilex = tile % 24; tiley = tile / 24;
    } else if (r < 4608) {
        int tile = r - 2304;
        src = W1 + (size_t)l * DD * FFD;
        dst = w16 + base + 4 * LW_QKVO;
        K = DD; N = FFD;
        tilex = tile % 96; tiley = tile / 96;
    } else {
        int tile = r - 4608;
        src = W2 + (size_t)l * FFD * DD;
        dst = w16 + base + 4 * LW_QKVO + LW_FF;
        K = FFD; N = DD;
        tilex = tile % 24; tiley = tile / 24;
    }

    int tx = threadIdx.x & 31, ty = threadIdx.x >> 5;   // (32,8) flattened
    int nx = tilex * 32 + tx;
    int ky = tiley * 32;
#pragma unroll
    for (int i = 0; i < 4; i++)
        t[ty + i*8][tx] = src[(size_t)(ky + ty + i*8) * N + nx];
    __syncthreads();
    int kx = tiley * 32 + tx;
    int ny = tilex * 32;
#pragma unroll
    for (int i = 0; i < 4; i++)
        dst[(size_t)(ny + ty + i*8) * K + kx] = __float2half_rn(t[tx][ty + i*8]);
}

__global__ __launch_bounds__(256)
void concat_bias_kernel(const float* __restrict__ bq, const float* __restrict__ bk,
                        const float* __restrict__ bv, float* __restrict__ cb)
{
    int idx = blockIdx.x * 256 + threadIdx.x;
    if (idx >= LL * QKVN) return;
    int l = idx / QKVN, j = idx % QKVN;
    float v;
    if (j < DD)            v = bq[l*DD + j];
    else if (j < 2*DD)     v = bk[l*DD + j - DD];
    else                   v = bv[l*DD + j - 2*DD];
    cb[idx] = v;
}

// ---------------------------------------------------------------------------
// Embedding + LayerNorm -> x fp32 + (hi,lo) fp16 split
// ---------------------------------------------------------------------------
__global__ __launch_bounds__(256)
void embed_ln_kernel(const int* __restrict__ ids, const int* __restrict__ tt,
                     const float* __restrict__ we, const float* __restrict__ pe,
                     const float* __restrict__ te, const float* __restrict__ lg,
                     const float* __restrict__ lb, float* __restrict__ x,
                     __half* __restrict__ xhi, __half* __restrict__ xlo)
{
    int row = blockIdx.x;
    int s   = row % SS;
    int id  = ids[row];
    int t   = tt[row];
    int tid = threadIdx.x;
    const float* wr = we + (size_t)id * DD;
    const float* pr = pe + (size_t)s  * DD;
    const float* tr = te + (size_t)t  * DD;
    float v[3]; float sum = 0.f, sq = 0.f;
#pragma unroll
    for (int i = 0; i < 3; i++) {
        int d = tid + i * 256;
        float y = wr[d] + pr[d] + tr[d];
        v[i] = y; sum += y; sq += y * y;
    }
    __shared__ float sh1[256], sh2[256];
    sh1[tid] = sum; sh2[tid] = sq;
    __syncthreads();
    for (int st = 128; st > 0; st >>= 1) {
        if (tid < st) { sh1[tid] += sh1[tid+st]; sh2[tid] += sh2[tid+st]; }
        __syncthreads();
    }
    float mu  = sh1[0] * (1.f/768.f);
    float var = fmaxf(sh2[0] * (1.f/768.f) - mu*mu, 0.f);
    float inv = rsqrtf(var + 1e-12f);
#pragma unroll
    for (int i = 0; i < 3; i++) {
        int d = tid + i * 256;
        float y = (v[i]-mu)*inv*lg[d] + lb[d];
        size_t o = (size_t)row*DD + d;
        x[o] = y;
        __half h, l; split2h(y, h, l);
        xhi[o] = h; xlo[o] = l;
    }
}

// ---------------------------------------------------------------------------
// Residual + bias + LayerNorm -> x fp32 (in place) + fp16 split
// ---------------------------------------------------------------------------
__global__ __launch_bounds__(256)
void ln_res_kernel(float* __restrict__ x, const float* __restrict__ val,
                   const float* __restrict__ bias, const float* __restrict__ lg,
                   const float* __restrict__ lb,
                   __half* __restrict__ xhi, __half* __restrict__ xlo)
{
    int row = blockIdx.x;
    int tid = threadIdx.x;
    float v[3]; float sum = 0.f, sq = 0.f;
#pragma unroll
    for (int i = 0; i < 3; i++) {
        int d = tid + i * 256;
        float y = x[(size_t)row*DD + d] + val[(size_t)row*DD + d] + bias[d];
        v[i] = y; sum += y; sq += y * y;
    }
    __shared__ float sh1[256], sh2[256];
    sh1[tid] = sum; sh2[tid] = sq;
    __syncthreads();
    for (int st = 128; st > 0; st >>= 1) {
        if (tid < st) { sh1[tid] += sh1[tid+st]; sh2[tid] += sh2[tid+st]; }
        __syncthreads();
    }
    float mu  = sh1[0] * (1.f/768.f);
    float var = fmaxf(sh2[0] * (1.f/768.f) - mu*mu, 0.f);
    float inv = rsqrtf(var + 1e-12f);
#pragma unroll
    for (int i = 0; i < 3; i++) {
        int d = tid + i * 256;
        float y = (v[i]-mu)*inv*lg[d] + lb[d];
        size_t o = (size_t)row*DD + d;
        x[o] = y;
        __half h, l; split2h(y, h, l);
        xhi[o] = h; xlo[o] = l;
    }
}

// ---------------------------------------------------------------------------
// HMMA GEMM: C[M,N] = A[M,K] @ Wt[N,K]^T.
// A split (fp16 hi+lo), W rounded to fp16 once -> 2 mma terms.
// CTA tile 128x128x32, 8 warps (2m x 4n), mma m16n8k16, 3-stage cp.async.
// MODE 0: C fp32   MODE 1: +bias -> fp16 out (Chi)   MODE 2: +bias+gelu -> fp16 split
// ---------------------------------------------------------------------------
__device__ __forceinline__ float gelu_exact(float x) {
    return 0.5f * x * (1.0f + erff(x * 0.70710678118654752f));
}

#define GPAD 40                  // smem row stride (elements) -> 80 bytes
#define TSZB (128*GPAD*2)        // 10240 B per 128x32 fp16 tile
#define STAGEB (3*TSZB)          // Ahi, Alo, W  (30720 B)
#define NSTAGE 3
#define GEMM_SMEM (NSTAGE*STAGEB)   // 92160 B

__device__ __forceinline__ void gemm_load_stage(
    uint32_t sbase, const __half* __restrict__ Ahi, const __half* __restrict__ Alo,
    const __half* __restrict__ W, int bm, int bn, int k0, int K, int tid)
{
    const __half* bases[3] = { Ahi, Alo, W };
#pragma unroll
    for (int i = 0; i < 6; i++) {
        const int tile = i >> 1;                 // 0..2 (compile-time)
        int f = ((i & 1) << 8) + tid;            // 0..511
        int r  = f >> 2;                         // 0..127
        int cq = f & 3;                          // 16B chunk
        int rowg = ((tile < 2) ? bm : bn) + r;
        const __half* src = bases[tile] + (size_t)rowg * K + k0 + cq * 8;
        uint32_t dst = sbase + tile * TSZB + r * (GPAD*2) + cq * 16;
        CP_ASYNC16(dst, src);
    }
}

template<int MODE>
__global__ __launch_bounds__(256)
void gemm_mma(const __half* __restrict__ Ahi, const __half* __restrict__ Alo,
              const __half* __restrict__ W, const float* __restrict__ bias,
              float* __restrict__ C, __half* __restrict__ Chi, __half* __restrict__ Clo,
              int N, int K)
{
    extern __shared__ char smem[];
    const uint32_t sb = smem_to_u32(smem);
    const int tid  = threadIdx.x;
    const int wid  = tid >> 5;
    const int lane = tid & 31;
    const int wm = wid >> 2;          // 0..1
    const int wn = wid & 3;           // 0..3
    const int bm = blockIdx.y * 128;
    const int bn = blockIdx.x * 128;

    float acc[4][4][4];
#pragma unroll
    for (int mi = 0; mi < 4; mi++)
#pragma unroll
        for (int ni = 0; ni < 4; ni++)
#pragma unroll
            for (int p = 0; p < 4; p++) acc[mi][ni][p] = 0.f;

    const int nchunks = K >> 5;

    gemm_load_stage(sb, Ahi, Alo, W, bm, bn, 0, K, tid);
    CP_COMMIT;
    gemm_load_stage(sb + STAGEB, Ahi, Alo, W, bm, bn, 32, K, tid);
    CP_COMMIT;

    const int arow = wm * 64 + (lane & 15);
    const int acolh = (lane >> 4) * 8;
    const int brow = wn * 32 + (lane & 7);
    const int bcolh = ((lane >> 3) & 1) * 8;

    for (int c = 0; c < nchunks; c++) {
        if (c + 1 < nchunks) { CP_WAIT1; } else { CP_WAIT0; }
        __syncthreads();
        if (c + 2 < nchunks) {
            int s2 = (c + 2) % NSTAGE;
            gemm_load_stage(sb + s2 * STAGEB, Ahi, Alo, W, bm, bn,
                            (c + 2) << 5, K, tid);
            CP_COMMIT;
        }

        const uint32_t st = sb + (c % NSTAGE) * STAGEB;
        const uint32_t aHiB = st;
        const uint32_t aLoB = st + TSZB;
        const uint32_t wB   = st + 2*TSZB;

#pragma unroll
        for (int kk = 0; kk < 32; kk += 16) {
            uint32_t ah[4][4], al[4][4];
#pragma unroll
            for (int mi = 0; mi < 4; mi++) {
                uint32_t off = (uint32_t)((arow + mi*16) * (GPAD*2) + (kk + acolh) * 2);
                ldsm_x4(aHiB + off, ah[mi][0], ah[mi][1], ah[mi][2], ah[mi][3]);
                ldsm_x4(aLoB + off, al[mi][0], al[mi][1], al[mi][2], al[mi][3]);
            }
#pragma unroll
            for (int ni = 0; ni < 4; ni++) {
                uint32_t off = (uint32_t)((brow + ni*8) * (GPAD*2) + (kk + bcolh) * 2);
                uint32_t bw[2];
                ldsm_x2(wB + off, bw[0], bw[1]);
#pragma unroll
                for (int mi = 0; mi < 4; mi++) {
                    mma_f16(acc[mi][ni], ah[mi], bw);
                    mma_f16(acc[mi][ni], al[mi], bw);
                }
            }
        }
    }

    // epilogue
    const int qrow = lane >> 2;
    const int qcol = (lane & 3) * 2;
#pragma unroll
    for (int mi = 0; mi < 4; mi++) {
#pragma unroll
        for (int p = 0; p < 2; p++) {
            int row = bm + wm*64 + mi*16 + qrow + p*8;
#pragma unroll
            for (int ni = 0; ni < 4; ni++) {
                int col = bn + wn*32 + ni*8 + qcol;
                float v0 = acc[mi][ni][p*2 + 0];
                float v1 = acc[mi][ni][p*2 + 1];
                if (MODE >= 1) { v0 += bias[col]; v1 += bias[col+1]; }
                if (MODE == 0) {
                    float2 o; o.x = v0; o.y = v1;
                    *(float2*)&C[(size_t)row * N + col] = o;
                } else if (MODE == 1) {
                    *(__half2*)&Chi[(size_t)row * N + col] =
                        __halves2half2(__float2half_rn(v0), __float2half_rn(v1));
                } else {
                    v0 = gelu_exact(v0); v1 = gelu_exact(v1);
                    __half h0,l0,h1,l1;
                    split2h(v0,h0,l0); split2h(v1,h1,l1);
                    *(__half2*)&Chi[(size_t)row * N + col] = __halves2half2(h0,h1);
                    *(__half2*)&Clo[(size_t)row * N + col] = __halves2half2(l0,l1);
                }
            }
        }
    }
}

// ---------------------------------------------------------------------------
// Attention: block = (32-query tile, h, b), 256 threads, fp32 compute,
// reads fused qkv (fp16), writes output pre-split as fp16 hi/lo [M, D].
// ---------------------------------------------------------------------------
#define AT_QS   0            // [32][72]
#define AT_CH   2304         // [64][72]
#define AT_S    6912         // [32][257]
#define AT_RED  15136        // [32][8]
#define AT_RMAX 15392        // [32]
#define AT_RSUM 15424        // [32]
#define AT_MB   15456        // [256]
#define AT_TOTALF 15712
#define AT_SMEM_BYTES (AT_TOTALF*4)

__global__ __launch_bounds__(256)
void attn_kernel(const __half* __restrict__ qkv, const int* __restrict__ mask,
                 __half* __restrict__ ohi, __half* __restrict__ olo)
{
    extern __shared__ float sm[];
    float* Qs   = sm + AT_QS;
    float* CH   = sm + AT_CH;
    float* S    = sm + AT_S;
    float* RED  = sm + AT_RED;
    float* RMAX = sm + AT_RMAX;
    float* RSUM = sm + AT_RSUM;
    float* MB   = sm + AT_MB;

    const int qt = blockIdx.x, h = blockIdx.y, b = blockIdx.z;
    const int tid = threadIdx.x;
    const int qq = tid >> 3;       // 0..31
    const int sub = tid & 7;       // 0..7
    const int rowbase = b * SS;
    const int q0 = qt * 32;
    const int hoff = h * DHD;

    MB[tid] = (1.0f - (float)mask[rowbase + tid]) * -10000.0f;

    // Q tile: 32 rows x 64 (as 32 half2 per row)
#pragma unroll
    for (int i = 0; i < 4; i++) {
        int f = tid + i * 256;         // 0..1023
        int r = f >> 5, d2 = f & 31;
        __half2 hv = *(const __half2*)&qkv[(size_t)(rowbase + q0 + r) * QKVN + hoff + d2*2];
        float2 fv = __half22float2(hv);
        Qs[r * 72 + d2*2]     = fv.x;
        Qs[r * 72 + d2*2 + 1] = fv.y;
    }
    __syncthreads();

    // ---- scores (K at offset +DD) ----
    for (int kc = 0; kc < 4; kc++) {
#pragma unroll
        for (int i = 0; i < 8; i++) {
            int f = tid + i * 256;     // 0..2047
            int r = f >> 5, d2 = f & 31;
            __half2 hv = *(const __half2*)&qkv[(size_t)(rowbase + kc * 64 + r) * QKVN + DD + hoff + d2*2];
            float2 fv = __half22float2(hv);
            CH[r * 72 + d2*2]     = fv.x;
            CH[r * 72 + d2*2 + 1] = fv.y;
        }
        __syncthreads();
#pragma unroll
        for (int i = 0; i < 8; i++) {
            int j = sub + i * 8;
            float s = 0.f;
#pragma unroll
            for (int d = 0; d < 64; d += 4) {
                float4 qa = *(const float4*)&Qs[qq * 72 + d];
                float4 ka = *(const float4*)&CH[j * 72 + d];
                s += qa.x * ka.x + qa.y * ka.y + qa.z * ka.z + qa.w * ka.w;
            }
            S[qq * 257 + kc * 64 + j] = s * 0.125f + MB[kc * 64 + j];
        }
        __syncthreads();
    }

    // ---- softmax ----
    {
        float m = -3.4e38f;
#pragma unroll
        for (int i = 0; i < 32; i++) m = fmaxf(m, S[qq * 257 + sub + i * 8]);
        RED[qq * 8 + sub] = m;
        __syncthreads();
        if (sub == 0) {
            float mm = RED[qq * 8];
#pragma unroll
            for (int i = 1; i < 8; i++) mm = fmaxf(mm, RED[qq * 8 + i]);
            RMAX[qq] = mm;
        }
        __syncthreads();
        float mx = RMAX[qq];
        float ssum = 0.f;
#pragma unroll
        for (int i = 0; i < 32; i++) {
            int idx = qq * 257 + sub + i * 8;
            float e = __expf(S[idx] - mx);
            S[idx] = e;
            ssum += e;
        }
        RED[qq * 8 + sub] = ssum;
        __syncthreads();
        if (sub == 0) {
            float t = 0.f;
#pragma unroll
            for (int i = 0; i < 8; i++) t += RED[qq * 8 + i];
            RSUM[qq] = t;
        }
        __syncthreads();
    }

    // ---- O = P @ V  (V at offset +2*DD) ----
    float acc[8];
#pragma unroll
    for (int m2 = 0; m2 < 8; m2++) acc[m2] = 0.f;
    const int d0 = sub * 8;
    for (int vc = 0; vc < 4; vc++) {
        __syncthreads();
#pragma unroll
        for (int i = 0; i < 8; i++) {
            int f = tid + i * 256;
            int r = f >> 5, d2 = f & 31;
            __half2 hv = *(const __half2*)&qkv[(size_t)(rowbase + vc * 64 + r) * QKVN + 2*DD + hoff + d2*2];
            float2 fv = __half22float2(hv);
            CH[r * 72 + d2*2]     = fv.x;
            CH[r * 72 + d2*2 + 1] = fv.y;
        }
        __syncthreads();
#pragma unroll 4
        for (int j = 0; j < 64; j++) {
            float p = S[qq * 257 + vc * 64 + j];
            float4 va = *(const float4*)&CH[j * 72 + d0];
            float4 vb = *(const float4*)&CH[j * 72 + d0 + 4];
            acc[0] += p * va.x; acc[1] += p * va.y;
            acc[2] += p * va.z; acc[3] += p * va.w;
            acc[4] += p * vb.x; acc[5] += p * vb.y;
            acc[6] += p * vb.z; acc[7] += p * vb.w;
        }
    }
    float inv = 1.0f / RSUM[qq];
    size_t obase = (size_t)(rowbase + q0 + qq) * DD + hoff + d0;
#pragma unroll
    for (int m2 = 0; m2 < 8; m2 += 2) {
        float y0 = acc[m2] * inv, y1 = acc[m2+1] * inv;
        __half h0,l0,h1,l1;
        split2h(y0,h0,l0); split2h(y1,h1,l1);
        *(__half2*)&ohi[obase + m2] = __halves2half2(h0,h1);
        *(__half2*)&olo[obase + m2] = __halves2half2(l0,l1);
    }
}

// ---------------------------------------------------------------------------
// sense key projection + final top-2
// ---------------------------------------------------------------------------
__global__ __launch_bounds__(64)
void sense_k_kernel(const float* __restrict__ sense, const float* __restrict__ Wk,
                    float* __restrict__ sk)
{
    int j = blockIdx.x, t = threadIdx.x;
    float s = 0.f;
    for (int d = 0; d < DD; d++)
        s += sense[(size_t)j*DD + d] * Wk[(size_t)d*NATT + t];
    sk[j*NATT + t] = s;
}

__global__ __launch_bounds__(64)
void final_kernel(const float* __restrict__ x, const int* __restrict__ loc,
                  const float* __restrict__ Wq, const float* __restrict__ sk,
                  float* __restrict__ out)
{
    int b = blockIdx.x, t = threadIdx.x;
    __shared__ float pun[DD];
    __shared__ float pq[NATT];
    __shared__ float sc[NSENSE];

    int r = b*SS + loc[b];
    for (int d = t; d < DD; d += 64) pun[d] = x[(size_t)r*DD + d];
    __syncthreads();

    float s = 0.f;
    for (int d = 0; d < DD; d++) s += pun[d] * Wq[(size_t)d*NATT + t];
    pq[t] = s;
    __syncthreads();

    float sv = 0.f;
#pragma unroll
    for (int u = 0; u < NATT; u++) sv += pq[u] * sk[t*NATT + u];
    sc[t] = sv * 0.125f;
    __syncthreads();

    if (t == 0) {
        int i1 = 0; float b1v = sc[0];
        for (int i = 1; i < NSENSE; i++) if (sc[i] > b1v) { b1v = sc[i]; i1 = i; }
        int i2 = -1; float b2v = -3.4e38f;
        for (int i = 0; i < NSENSE; i++) if (i != i1 && sc[i] > b2v) { b2v = sc[i]; i2 = i; }
        out[b*2+0] = (float)i1;
        out[b*2+1] = (float)i2;
    }
}

// ---------------------------------------------------------------------------
// launch
// ---------------------------------------------------------------------------
extern "C" void kernel_launch(void* const* d_in, const int* in_sizes, int n_in,
                              void* d_out, int out_size)
{
    const int*   input_ids = (const int*)  d_in[0];
    const int*   type_ids  = (const int*)  d_in[1];
    const int*   attn_mask = (const int*)  d_in[2];
    const int*   location  = (const int*)  d_in[3];
    const float* sense_emb = (const float*)d_in[4];
    const float* word_emb  = (const float*)d_in[5];
    const float* pos_emb   = (const float*)d_in[6];
    const float* type_emb  = (const float*)d_in[7];
    const float* emb_ln_g  = (const float*)d_in[8];
    const float* emb_ln_b  = (const float*)d_in[9];
    const float* Wq = (const float*)d_in[10];
    const float* bq = (const float*)d_in[11];
    const float* Wk = (const float*)d_in[12];
    const float* bk = (const float*)d_in[13];
    const float* Wv = (const float*)d_in[14];
    const float* bv = (const float*)d_in[15];
    const float* Wo = (const float*)d_in[16];
    const float* bo = (const float*)d_in[17];
    const float* ln1_g = (const float*)d_in[18];
    const float* ln1_b = (const float*)d_in[19];
    const float* W1 = (const float*)d_in[20];
    const float* b1 = (const float*)d_in[21];
    const float* W2 = (const float*)d_in[22];
    const float* b2 = (const float*)d_in[23];
    const float* ln2_g = (const float*)d_in[24];
    const float* ln2_b = (const float*)d_in[25];
    const float* att_Wq = (const float*)d_in[26];
    const float* att_Wk = (const float*)d_in[27];

    float *x, *tmp, *sk, *cbias;
    __half *qkv, *w16, *ahi, *alo, *bhi, *blo;
    cudaGetSymbolAddress((void**)&x,     g_x);
    cudaGetSymbolAddress((void**)&qkv,   g_qkv);
    cudaGetSymbolAddress((void**)&tmp,   g_tmp);
    cudaGetSymbolAddress((void**)&sk,    g_sk);
    cudaGetSymbolAddress((void**)&cbias, g_cbias);
    cudaGetSymbolAddress((void**)&w16,   g_w16);
    cudaGetSymbolAddress((void**)&ahi,   g_ahi);
    cudaGetSymbolAddress((void**)&alo,   g_alo);
    cudaGetSymbolAddress((void**)&bhi,   g_bhi);
    cudaGetSymbolAddress((void**)&blo,   g_blo);

    cudaFuncSetAttribute(gemm_mma<0>, cudaFuncAttributeMaxDynamicSharedMemorySize, GEMM_SMEM);
    cudaFuncSetAttribute(gemm_mma<1>, cudaFuncAttributeMaxDynamicSharedMemorySize, GEMM_SMEM);
    cudaFuncSetAttribute(gemm_mma<2>, cudaFuncAttributeMaxDynamicSharedMemorySize, GEMM_SMEM);
    cudaFuncSetAttribute(attn_kernel, cudaFuncAttributeMaxDynamicSharedMemorySize, AT_SMEM_BYTES);

    // launch order matters for ncu (-s 5): [0] transpose_all, [1] concat,
    // [2] embed_ln, [3] gemm_qkv, [4] attn, [5] gemm_wo  <-- profiled
    transpose_all_kernel<<<LL*TILES_PER_LAYER, 256>>>(Wq, Wk, Wv, Wo, W1, W2, w16);
    concat_bias_kernel<<<(LL*QKVN + 255)/256, 256>>>(bq, bk, bv, cbias);
    embed_ln_kernel<<<MM, 256>>>(input_ids, type_ids, word_emb, pos_emb,
                                 type_emb, emb_ln_g, emb_ln_b, x, ahi, alo);

    dim3 gQKV(QKVN/128, MM/128);  // (18, 64)
    dim3 gD(DD/128, MM/128);      // (6, 64)
    dim3 gF(FFD/128, MM/128);     // (24, 64)

    for (int l = 0; l < LL; l++) {
        size_t base = (size_t)l * LWSTRIDE;
        const __half* wqkv = w16 + base;                       // [2304,768]
        const __half* wo   = w16 + base + 3*LW_QKVO;           // [768,768]
        const __half* w1   = w16 + base + 4*LW_QKVO;           // [3072,768]
        const __half* w2   = w16 + base + 4*LW_QKVO + LW_FF;   // [768,3072]

        gemm_mma<1><<<gQKV, 256, GEMM_SMEM>>>(ahi, alo, wqkv, cbias + l*QKVN,
                                              nullptr, qkv, nullptr, QKVN, DD);

        attn_kernel<<<dim3(SS/32, HH, BB), 256, AT_SMEM_BYTES>>>(qkv, attn_mask, ahi, alo);

        gemm_mma<0><<<gD, 256, GEMM_SMEM>>>(ahi, alo, wo, nullptr, tmp,
                                            nullptr, nullptr, DD, DD);
        ln_res_kernel<<<MM, 256>>>(x, tmp, bo + l*DD, ln1_g + l*DD, ln1_b + l*DD, ahi, alo);

        gemm_mma<2><<<gF, 256, GEMM_SMEM>>>(ahi, alo, w1, b1 + l*FFD,
                                            nullptr, bhi, blo, FFD, DD);
        gemm_mma<0><<<gD, 256, GEMM_SMEM>>>(bhi, blo, w2, nullptr, tmp,
                                            nullptr, nullptr, DD, FFD);
        ln_res_kernel<<<MM, 256>>>(x, tmp, b2 + l*DD, ln2_g + l*DD, ln2_b + l*DD, ahi, alo);
    }

    sense_k_kernel<<<NSENSE, NATT>>>(sense_emb, att_Wk, sk);
    final_kernel<<<BB, 64>>>(x, location, att_Wq, sk, (float*)d_out);
}

// round 9
// speedup vs baseline: 2.1776x; 1.6762x over previous
#include <cuda_runtime.h>
#include <cuda_fp16.h>
#include <math.h>
#include <stdint.h>

// ---------------------------------------------------------------------------
// Problem constants
// ---------------------------------------------------------------------------
#define BB 32
#define SS 256
#define MM (BB*SS)        // 8192 rows
#define DD 768
#define HH 12
#define DHD 64
#define FFD 3072
#define LL 12
#define NSENSE 64
#define NATT 64
#define QKVN (3*DD)       // 2304

#define LW_QKVO ((size_t)DD*DD)
#define LW_FF   ((size_t)DD*FFD)
#define LWSTRIDE (4*LW_QKVO + 2*LW_FF)

// ---------------------------------------------------------------------------
// Scratch (static __device__ arrays; no runtime allocation allowed)
// ---------------------------------------------------------------------------
__device__ float  g_x  [(size_t)MM*DD];        // residual stream (fp32)
__device__ __half g_qkv[(size_t)MM*QKVN];      // fused QKV output (fp16)
__device__ float  g_tmp[(size_t)MM*DD];        // gemm output before LN
__device__ float  g_sk [NSENSE*NATT];
__device__ float  g_cbias[LL*QKVN];            // concatenated qkv bias

__device__ __half g_w16 [LL*LWSTRIDE];         // transposed weights [N,K] fp16
__device__ __half g_ahi [(size_t)MM*DD];       // activation hi (fp16)
__device__ __half g_alo [(size_t)MM*DD];       // activation lo (fp16)
__device__ __half g_bhi [(size_t)MM*FFD];      // ffn hidden hi
__device__ __half g_blo [(size_t)MM*FFD];      // ffn hidden lo

// ---------------------------------------------------------------------------
// asm helpers (sm_80-era features, legal on compute_103)
// ---------------------------------------------------------------------------
__device__ __forceinline__ uint32_t smem_to_u32(const void* smem_ptr) {
    uint32_t addr;
    asm("{ .reg .u64 tmp; cvta.to.shared.u64 tmp, %1; cvt.u32.u64 %0, tmp; }"
        : "=r"(addr) : "l"(smem_ptr));
    return addr;
}
#define CP_ASYNC16(dst_u32, src_ptr) \
    asm volatile("cp.async.cg.shared.global [%0], [%1], 16;" \
        :: "r"(dst_u32), "l"(src_ptr))
#define CP_COMMIT asm volatile("cp.async.commit_group;" ::: "memory")
#define CP_WAIT0  asm volatile("cp.async.wait_group 0;" ::: "memory")
#define CP_WAIT1  asm volatile("cp.async.wait_group 1;" ::: "memory")

__device__ __forceinline__ void ldsm_x4(uint32_t addr, uint32_t& r0, uint32_t& r1,
                                        uint32_t& r2, uint32_t& r3) {
    asm volatile("ldmatrix.sync.aligned.m8n8.x4.shared.b16 {%0,%1,%2,%3}, [%4];"
        : "=r"(r0), "=r"(r1), "=r"(r2), "=r"(r3) : "r"(addr));
}
__device__ __forceinline__ void ldsm_x2(uint32_t addr, uint32_t& r0, uint32_t& r1) {
    asm volatile("ldmatrix.sync.aligned.m8n8.x2.shared.b16 {%0,%1}, [%2];"
        : "=r"(r0), "=r"(r1) : "r"(addr));
}
__device__ __forceinline__ void ldsm_x2_trans(uint32_t addr, uint32_t& r0, uint32_t& r1) {
    asm volatile("ldmatrix.sync.aligned.m8n8.x2.trans.shared.b16 {%0,%1}, [%2];"
        : "=r"(r0), "=r"(r1) : "r"(addr));
}
__device__ __forceinline__ void mma_f16(float* c, const uint32_t* a, const uint32_t* b) {
    asm volatile(
        "mma.sync.aligned.m16n8k16.row.col.f32.f16.f16.f32 "
        "{%0,%1,%2,%3}, {%4,%5,%6,%7}, {%8,%9}, {%0,%1,%2,%3};"
        : "+f"(c[0]), "+f"(c[1]), "+f"(c[2]), "+f"(c[3])
        : "r"(a[0]), "r"(a[1]), "r"(a[2]), "r"(a[3]), "r"(b[0]), "r"(b[1]));
}

__device__ __forceinline__ void split2h(float f, __half& h, __half& l) {
    h = __float2half_rn(f);
    l = __float2half_rn(f - __half2float(h));
}

// ---------------------------------------------------------------------------
// weight prep: ALL transposes in ONE launch.
// ---------------------------------------------------------------------------
#define TILES_PER_LAYER 6912

__global__ __launch_bounds__(256)
void transpose_all_kernel(const float* __restrict__ Wq, const float* __restrict__ Wk,
                          const float* __restrict__ Wv, const float* __restrict__ Wo,
                          const float* __restrict__ W1, const float* __restrict__ W2,
                          __half* __restrict__ w16)
{
    __shared__ float t[32][33];
    int bid = blockIdx.x;
    int l = bid / TILES_PER_LAYER;
    int r = bid % TILES_PER_LAYER;

    const float* src;
    __half* dst;
    int K, N, tilex, tiley;
    size_t base = (size_t)l * LWSTRIDE;

    if (r < 2304) {
        int m = r / 576;
        int tile = r % 576;
        const float* srcs0 = (m == 0) ? Wq : (m == 1) ? Wk : (m == 2) ? Wv : Wo;
        src = srcs0 + (size_t)l * DD * DD;
        dst = w16 + base + (size_t)m * LW_QKVO;
        K = DD; N = DD;
        tilex = tile % 24; tiley = tile / 24;
    } else if (r < 4608) {
        int tile = r - 2304;
        src = W1 + (size_t)l * DD * FFD;
        dst = w16 + base + 4 * LW_QKVO;
        K = DD; N = FFD;
        tilex = tile % 96; tiley = tile / 96;
    } else {
        int tile = r - 4608;
        src = W2 + (size_t)l * FFD * DD;
        dst = w16 + base + 4 * LW_QKVO + LW_FF;
        K = FFD; N = DD;
        tilex = tile % 24; tiley = tile / 24;
    }

    int tx = threadIdx.x & 31, ty = threadIdx.x >> 5;
    int nx = tilex * 32 + tx;
    int ky = tiley * 32;
#pragma unroll
    for (int i = 0; i < 4; i++)
        t[ty + i*8][tx] = src[(size_t)(ky + ty + i*8) * N + nx];
    __syncthreads();
    int kx = tiley * 32 + tx;
    int ny = tilex * 32;
#pragma unroll
    for (int i = 0; i < 4; i++)
        dst[(size_t)(ny + ty + i*8) * K + kx] = __float2half_rn(t[tx][ty + i*8]);
}

__global__ __launch_bounds__(256)
void concat_bias_kernel(const float* __restrict__ bq, const float* __restrict__ bk,
                        const float* __restrict__ bv, float* __restrict__ cb)
{
    int idx = blockIdx.x * 256 + threadIdx.x;
    if (idx >= LL * QKVN) return;
    int l = idx / QKVN, j = idx % QKVN;
    float v;
    if (j < DD)            v = bq[l*DD + j];
    else if (j < 2*DD)     v = bk[l*DD + j - DD];
    else                   v = bv[l*DD + j - 2*DD];
    cb[idx] = v;
}

// ---------------------------------------------------------------------------
// Embedding + LayerNorm -> x fp32 + (hi,lo) fp16 split
// ---------------------------------------------------------------------------
__global__ __launch_bounds__(256)
void embed_ln_kernel(const int* __restrict__ ids, const int* __restrict__ tt,
                     const float* __restrict__ we, const float* __restrict__ pe,
                     const float* __restrict__ te, const float* __restrict__ lg,
                     const float* __restrict__ lb, float* __restrict__ x,
                     __half* __restrict__ xhi, __half* __restrict__ xlo)
{
    int row = blockIdx.x;
    int s   = row % SS;
    int id  = ids[row];
    int t   = tt[row];
    int tid = threadIdx.x;
    const float* wr = we + (size_t)id * DD;
    const float* pr = pe + (size_t)s  * DD;
    const float* tr = te + (size_t)t  * DD;
    float v[3]; float sum = 0.f, sq = 0.f;
#pragma unroll
    for (int i = 0; i < 3; i++) {
        int d = tid + i * 256;
        float y = wr[d] + pr[d] + tr[d];
        v[i] = y; sum += y; sq += y * y;
    }
    __shared__ float sh1[256], sh2[256];
    sh1[tid] = sum; sh2[tid] = sq;
    __syncthreads();
    for (int st = 128; st > 0; st >>= 1) {
        if (tid < st) { sh1[tid] += sh1[tid+st]; sh2[tid] += sh2[tid+st]; }
        __syncthreads();
    }
    float mu  = sh1[0] * (1.f/768.f);
    float var = fmaxf(sh2[0] * (1.f/768.f) - mu*mu, 0.f);
    float inv = rsqrtf(var + 1e-12f);
#pragma unroll
    for (int i = 0; i < 3; i++) {
        int d = tid + i * 256;
        float y = (v[i]-mu)*inv*lg[d] + lb[d];
        size_t o = (size_t)row*DD + d;
        x[o] = y;
        __half h, l; split2h(y, h, l);
        xhi[o] = h; xlo[o] = l;
    }
}

// ---------------------------------------------------------------------------
// Residual + bias + LayerNorm -> x fp32 (in place) + fp16 split
// ---------------------------------------------------------------------------
__global__ __launch_bounds__(256)
void ln_res_kernel(float* __restrict__ x, const float* __restrict__ val,
                   const float* __restrict__ bias, const float* __restrict__ lg,
                   const float* __restrict__ lb,
                   __half* __restrict__ xhi, __half* __restrict__ xlo)
{
    int row = blockIdx.x;
    int tid = threadIdx.x;
    float v[3]; float sum = 0.f, sq = 0.f;
#pragma unroll
    for (int i = 0; i < 3; i++) {
        int d = tid + i * 256;
        float y = x[(size_t)row*DD + d] + val[(size_t)row*DD + d] + bias[d];
        v[i] = y; sum += y; sq += y * y;
    }
    __shared__ float sh1[256], sh2[256];
    sh1[tid] = sum; sh2[tid] = sq;
    __syncthreads();
    for (int st = 128; st > 0; st >>= 1) {
        if (tid < st) { sh1[tid] += sh1[tid+st]; sh2[tid] += sh2[tid+st]; }
        __syncthreads();
    }
    float mu  = sh1[0] * (1.f/768.f);
    float var = fmaxf(sh2[0] * (1.f/768.f) - mu*mu, 0.f);
    float inv = rsqrtf(var + 1e-12f);
#pragma unroll
    for (int i = 0; i < 3; i++) {
        int d = tid + i * 256;
        float y = (v[i]-mu)*inv*lg[d] + lb[d];
        size_t o = (size_t)row*DD + d;
        x[o] = y;
        __half h, l; split2h(y, h, l);
        xhi[o] = h; xlo[o] = l;
    }
}

// ---------------------------------------------------------------------------
// HMMA GEMM (unchanged from R8)
// ---------------------------------------------------------------------------
__device__ __forceinline__ float gelu_exact(float x) {
    return 0.5f * x * (1.0f + erff(x * 0.70710678118654752f));
}

#define GPAD 40
#define TSZB (128*GPAD*2)
#define STAGEB (3*TSZB)
#define NSTAGE 3
#define GEMM_SMEM (NSTAGE*STAGEB)   // 92160 B

__device__ __forceinline__ void gemm_load_stage(
    uint32_t sbase, const __half* __restrict__ Ahi, const __half* __restrict__ Alo,
    const __half* __restrict__ W, int bm, int bn, int k0, int K, int tid)
{
    const __half* bases[3] = { Ahi, Alo, W };
#pragma unroll
    for (int i = 0; i < 6; i++) {
        const int tile = i >> 1;
        int f = ((i & 1) << 8) + tid;
        int r  = f >> 2;
        int cq = f & 3;
        int rowg = ((tile < 2) ? bm : bn) + r;
        const __half* src = bases[tile] + (size_t)rowg * K + k0 + cq * 8;
        uint32_t dst = sbase + tile * TSZB + r * (GPAD*2) + cq * 16;
        CP_ASYNC16(dst, src);
    }
}

template<int MODE>
__global__ __launch_bounds__(256)
void gemm_mma(const __half* __restrict__ Ahi, const __half* __restrict__ Alo,
              const __half* __restrict__ W, const float* __restrict__ bias,
              float* __restrict__ C, __half* __restrict__ Chi, __half* __restrict__ Clo,
              int N, int K)
{
    extern __shared__ char smem[];
    const uint32_t sb = smem_to_u32(smem);
    const int tid  = threadIdx.x;
    const int wid  = tid >> 5;
    const int lane = tid & 31;
    const int wm = wid >> 2;
    const int wn = wid & 3;
    const int bm = blockIdx.y * 128;
    const int bn = blockIdx.x * 128;

    float acc[4][4][4];
#pragma unroll
    for (int mi = 0; mi < 4; mi++)
#pragma unroll
        for (int ni = 0; ni < 4; ni++)
#pragma unroll
            for (int p = 0; p < 4; p++) acc[mi][ni][p] = 0.f;

    const int nchunks = K >> 5;

    gemm_load_stage(sb, Ahi, Alo, W, bm, bn, 0, K, tid);
    CP_COMMIT;
    gemm_load_stage(sb + STAGEB, Ahi, Alo, W, bm, bn, 32, K, tid);
    CP_COMMIT;

    const int arow = wm * 64 + (lane & 15);
    const int acolh = (lane >> 4) * 8;
    const int brow = wn * 32 + (lane & 7);
    const int bcolh = ((lane >> 3) & 1) * 8;

    for (int c = 0; c < nchunks; c++) {
        if (c + 1 < nchunks) { CP_WAIT1; } else { CP_WAIT0; }
        __syncthreads();
        if (c + 2 < nchunks) {
            int s2 = (c + 2) % NSTAGE;
            gemm_load_stage(sb + s2 * STAGEB, Ahi, Alo, W, bm, bn,
                            (c + 2) << 5, K, tid);
            CP_COMMIT;
        }

        const uint32_t st = sb + (c % NSTAGE) * STAGEB;
        const uint32_t aHiB = st;
        const uint32_t aLoB = st + TSZB;
        const uint32_t wB   = st + 2*TSZB;

#pragma unroll
        for (int kk = 0; kk < 32; kk += 16) {
            uint32_t ah[4][4], al[4][4];
#pragma unroll
            for (int mi = 0; mi < 4; mi++) {
                uint32_t off = (uint32_t)((arow + mi*16) * (GPAD*2) + (kk + acolh) * 2);
                ldsm_x4(aHiB + off, ah[mi][0], ah[mi][1], ah[mi][2], ah[mi][3]);
                ldsm_x4(aLoB + off, al[mi][0], al[mi][1], al[mi][2], al[mi][3]);
            }
#pragma unroll
            for (int ni = 0; ni < 4; ni++) {
                uint32_t off = (uint32_t)((brow + ni*8) * (GPAD*2) + (kk + bcolh) * 2);
                uint32_t bw[2];
                ldsm_x2(wB + off, bw[0], bw[1]);
#pragma unroll
                for (int mi = 0; mi < 4; mi++) {
                    mma_f16(acc[mi][ni], ah[mi], bw);
                    mma_f16(acc[mi][ni], al[mi], bw);
                }
            }
        }
    }

    const int qrow = lane >> 2;
    const int qcol = (lane & 3) * 2;
#pragma unroll
    for (int mi = 0; mi < 4; mi++) {
#pragma unroll
        for (int p = 0; p < 2; p++) {
            int row = bm + wm*64 + mi*16 + qrow + p*8;
#pragma unroll
            for (int ni = 0; ni < 4; ni++) {
                int col = bn + wn*32 + ni*8 + qcol;
                float v0 = acc[mi][ni][p*2 + 0];
                float v1 = acc[mi][ni][p*2 + 1];
                if (MODE >= 1) { v0 += bias[col]; v1 += bias[col+1]; }
                if (MODE == 0) {
                    float2 o; o.x = v0; o.y = v1;
                    *(float2*)&C[(size_t)row * N + col] = o;
                } else if (MODE == 1) {
                    *(__half2*)&Chi[(size_t)row * N + col] =
                        __halves2half2(__float2half_rn(v0), __float2half_rn(v1));
                } else {
                    v0 = gelu_exact(v0); v1 = gelu_exact(v1);
                    __half h0,l0,h1,l1;
                    split2h(v0,h0,l0); split2h(v1,h1,l1);
                    *(__half2*)&Chi[(size_t)row * N + col] = __halves2half2(h0,h1);
                    *(__half2*)&Clo[(size_t)row * N + col] = __halves2half2(l0,l1);
                }
            }
        }
    }
}

// ---------------------------------------------------------------------------
// HMMA attention: block = (64-query tile, h, b), 256 threads (8 warps).
// S = Q @ K^T via mma (fp16 in, fp32 acc); block softmax; P fp16;
// O = P @ V via mma (V as B operand through ldmatrix.trans).
// ---------------------------------------------------------------------------
#define AHS 72      // half stride for Q/KV tiles (144B rows, conflict-free ldsm)
#define SST 264     // float stride for S
#define PST 264     // half stride for P

#define AT2_MB   0                       // 256 floats
#define AT2_RED  1024                    // 64*4 floats
#define AT2_MX   2048                    // 64 floats
#define AT2_INV  2304                    // 64 floats
#define AT2_Q    2560                    // 64*72 halves = 9216B
#define AT2_KV   11776                   // 64*72 halves = 9216B
#define AT2_S    20992                   // 64*264 floats = 67584B
#define AT2_P    88576                   // 64*264 halves = 33792B
#define AT2_SMEM 122368

__global__ __launch_bounds__(256)
void attn_mma_kernel(const __half* __restrict__ qkv, const int* __restrict__ mask,
                     __half* __restrict__ ohi, __half* __restrict__ olo)
{
    extern __shared__ char smc[];
    float*  MB  = (float*)(smc + AT2_MB);
    float*  RED = (float*)(smc + AT2_RED);
    float*  MX  = (float*)(smc + AT2_MX);
    float*  INV = (float*)(smc + AT2_INV);
    __half* Qs  = (__half*)(smc + AT2_Q);
    __half* KV  = (__half*)(smc + AT2_KV);
    float*  S   = (float*)(smc + AT2_S);
    __half* P   = (__half*)(smc + AT2_P);
    const uint32_t qb  = smem_to_u32(Qs);
    const uint32_t kvb = smem_to_u32(KV);
    const uint32_t pbb = smem_to_u32(P);

    const int qt = blockIdx.x, h = blockIdx.y, b = blockIdx.z;
    const int tid = threadIdx.x, wid = tid >> 5, lane = tid & 31;
    const int rowbase = b * SS;
    const int q0 = qt * 64;
    const int hoff = h * DHD;
    const int wm = wid >> 2, wn = wid & 3;

    MB[tid] = (1.0f - (float)mask[rowbase + tid]) * -10000.0f;

    // Q tile 64x64 fp16
#pragma unroll
    for (int i = 0; i < 8; i++) {
        int f = tid + i * 256;
        int r = f >> 5, d2 = f & 31;
        *(__half2*)&Qs[r * AHS + d2 * 2] =
            *(const __half2*)&qkv[(size_t)(rowbase + q0 + r) * QKVN + hoff + d2 * 2];
    }
    __syncthreads();

    // ---- scores: S[64 x 256] in 4 chunks of 64 keys ----
    for (int kc = 0; kc < 4; kc++) {
#pragma unroll
        for (int i = 0; i < 8; i++) {
            int f = tid + i * 256;
            int r = f >> 5, d2 = f & 31;
            *(__half2*)&KV[r * AHS + d2 * 2] =
                *(const __half2*)&qkv[(size_t)(rowbase + kc*64 + r) * QKVN + DD + hoff + d2*2];
        }
        __syncthreads();

        float acc[2][2][4];
#pragma unroll
        for (int mi = 0; mi < 2; mi++)
#pragma unroll
            for (int ni = 0; ni < 2; ni++)
#pragma unroll
                for (int p = 0; p < 4; p++) acc[mi][ni][p] = 0.f;

#pragma unroll
        for (int kk = 0; kk < 64; kk += 16) {
            uint32_t af[2][4];
#pragma unroll
            for (int mi = 0; mi < 2; mi++) {
                uint32_t off = (uint32_t)((wm*32 + mi*16 + (lane&15)) * (AHS*2) + (kk + (lane>>4)*8) * 2);
                ldsm_x4(qb + off, af[mi][0], af[mi][1], af[mi][2], af[mi][3]);
            }
#pragma unroll
            for (int ni = 0; ni < 2; ni++) {
                uint32_t off = (uint32_t)((wn*16 + ni*8 + (lane&7)) * (AHS*2) + (kk + ((lane>>3)&1)*8) * 2);
                uint32_t bf[2];
                ldsm_x2(kvb + off, bf[0], bf[1]);
#pragma unroll
                for (int mi = 0; mi < 2; mi++)
                    mma_f16(acc[mi][ni], af[mi], bf);
            }
        }

        {
            const int qrow = lane >> 2, qcol = (lane & 3) * 2;
#pragma unroll
            for (int mi = 0; mi < 2; mi++)
#pragma unroll
                for (int ni = 0; ni < 2; ni++) {
                    int rl = wm*32 + mi*16 + qrow;
                    int cl = kc*64 + wn*16 + ni*8 + qcol;
                    S[rl*SST + cl]       = acc[mi][ni][0]*0.125f + MB[cl];
                    S[rl*SST + cl+1]     = acc[mi][ni][1]*0.125f + MB[cl+1];
                    S[(rl+8)*SST + cl]   = acc[mi][ni][2]*0.125f + MB[cl];
                    S[(rl+8)*SST + cl+1] = acc[mi][ni][3]*0.125f + MB[cl+1];
                }
        }
        __syncthreads();
    }

    // ---- softmax over rows of S; write P fp16 ----
    {
        int row = tid >> 2, sub = tid & 3;
        float m = -3.4e38f;
#pragma unroll 8
        for (int i = 0; i < 64; i++) m = fmaxf(m, S[row*SST + sub + i*4]);
        RED[row*4 + sub] = m;
        __syncthreads();
        if (sub == 0)
            MX[row] = fmaxf(fmaxf(RED[row*4], RED[row*4+1]),
                            fmaxf(RED[row*4+2], RED[row*4+3]));
        __syncthreads();
        float mx = MX[row];
        float ssum = 0.f;
#pragma unroll 8
        for (int i = 0; i < 64; i++) {
            int c = sub + i*4;
            float e = __expf(S[row*SST + c] - mx);
            P[row*PST + c] = __float2half_rn(e);
            ssum += e;
        }
        RED[row*4 + sub] = ssum;
        __syncthreads();
        if (sub == 0)
            INV[row] = 1.0f / (RED[row*4] + RED[row*4+1] + RED[row*4+2] + RED[row*4+3]);
        __syncthreads();
    }

    // ---- O = P @ V ----
    float accO[2][2][4];
#pragma unroll
    for (int mi = 0; mi < 2; mi++)
#pragma unroll
        for (int ni = 0; ni < 2; ni++)
#pragma unroll
            for (int p = 0; p < 4; p++) accO[mi][ni][p] = 0.f;

    for (int kc = 0; kc < 4; kc++) {
#pragma unroll
        for (int i = 0; i < 8; i++) {
            int f = tid + i * 256;
            int r = f >> 5, d2 = f & 31;
            *(__half2*)&KV[r * AHS + d2 * 2] =
                *(const __half2*)&qkv[(size_t)(rowbase + kc*64 + r) * QKVN + 2*DD + hoff + d2*2];
        }
        __syncthreads();
#pragma unroll
        for (int kk = 0; kk < 64; kk += 16) {
            uint32_t af[2][4];
#pragma unroll
            for (int mi = 0; mi < 2; mi++) {
                uint32_t off = (uint32_t)((wm*32 + mi*16 + (lane&15)) * (PST*2) + (kc*64 + kk + (lane>>4)*8) * 2);
                ldsm_x4(pbb + off, af[mi][0], af[mi][1], af[mi][2], af[mi][3]);
            }
#pragma unroll
            for (int ni = 0; ni < 2; ni++) {
                uint32_t off = (uint32_t)((kk + (lane&15)) * (AHS*2) + (wn*16 + ni*8) * 2);
                uint32_t bf[2];
                ldsm_x2_trans(kvb + off, bf[0], bf[1]);
#pragma unroll
                for (int mi = 0; mi < 2; mi++)
                    mma_f16(accO[mi][ni], af[mi], bf);
            }
        }
        __syncthreads();
    }

    // ---- epilogue: normalize and write fp16 split ----
    {
        const int qrow = lane >> 2, qcol = (lane & 3) * 2;
#pragma unroll
        for (int mi = 0; mi < 2; mi++)
#pragma unroll
            for (int ni = 0; ni < 2; ni++)
#pragma unroll
                for (int p = 0; p < 2; p++) {
                    int rl = wm*32 + mi*16 + qrow + p*8;
                    int cl = wn*16 + ni*8 + qcol;
                    float inv = INV[rl];
                    float y0 = accO[mi][ni][p*2]     * inv;
                    float y1 = accO[mi][ni][p*2 + 1] * inv;
                    size_t ob = (size_t)(rowbase + q0 + rl) * DD + hoff + cl;
                    __half h0,l0,h1,l1;
                    split2h(y0,h0,l0); split2h(y1,h1,l1);
                    *(__half2*)&ohi[ob] = __halves2half2(h0,h1);
                    *(__half2*)&olo[ob] = __halves2half2(l0,l1);
                }
    }
}

// ---------------------------------------------------------------------------
// sense key projection + final top-2
// ---------------------------------------------------------------------------
__global__ __launch_bounds__(64)
void sense_k_kernel(const float* __restrict__ sense, const float* __restrict__ Wk,
                    float* __restrict__ sk)
{
    int j = blockIdx.x, t = threadIdx.x;
    float s = 0.f;
    for (int d = 0; d < DD; d++)
        s += sense[(size_t)j*DD + d] * Wk[(size_t)d*NATT + t];
    sk[j*NATT + t] = s;
}

__global__ __launch_bounds__(64)
void final_kernel(const float* __restrict__ x, const int* __restrict__ loc,
                  const float* __restrict__ Wq, const float* __restrict__ sk,
                  float* __restrict__ out)
{
    int b = blockIdx.x, t = threadIdx.x;
    __shared__ float pun[DD];
    __shared__ float pq[NATT];
    __shared__ float sc[NSENSE];

    int r = b*SS + loc[b];
    for (int d = t; d < DD; d += 64) pun[d] = x[(size_t)r*DD + d];
    __syncthreads();

    float s = 0.f;
    for (int d = 0; d < DD; d++) s += pun[d] * Wq[(size_t)d*NATT + t];
    pq[t] = s;
    __syncthreads();

    float sv = 0.f;
#pragma unroll
    for (int u = 0; u < NATT; u++) sv += pq[u] * sk[t*NATT + u];
    sc[t] = sv * 0.125f;
    __syncthreads();

    if (t == 0) {
        int i1 = 0; float b1v = sc[0];
        for (int i = 1; i < NSENSE; i++) if (sc[i] > b1v) { b1v = sc[i]; i1 = i; }
        int i2 = -1; float b2v = -3.4e38f;
        for (int i = 0; i < NSENSE; i++) if (i != i1 && sc[i] > b2v) { b2v = sc[i]; i2 = i; }
        out[b*2+0] = (float)i1;
        out[b*2+1] = (float)i2;
    }
}

// ---------------------------------------------------------------------------
// launch
// ---------------------------------------------------------------------------
extern "C" void kernel_launch(void* const* d_in, const int* in_sizes, int n_in,
                              void* d_out, int out_size)
{
    const int*   input_ids = (const int*)  d_in[0];
    const int*   type_ids  = (const int*)  d_in[1];
    const int*   attn_mask = (const int*)  d_in[2];
    const int*   location  = (const int*)  d_in[3];
    const float* sense_emb = (const float*)d_in[4];
    const float* word_emb  = (const float*)d_in[5];
    const float* pos_emb   = (const float*)d_in[6];
    const float* type_emb  = (const float*)d_in[7];
    const float* emb_ln_g  = (const float*)d_in[8];
    const float* emb_ln_b  = (const float*)d_in[9];
    const float* Wq = (const float*)d_in[10];
    const float* bq = (const float*)d_in[11];
    const float* Wk = (const float*)d_in[12];
    const float* bk = (const float*)d_in[13];
    const float* Wv = (const float*)d_in[14];
    const float* bv = (const float*)d_in[15];
    const float* Wo = (const float*)d_in[16];
    const float* bo = (const float*)d_in[17];
    const float* ln1_g = (const float*)d_in[18];
    const float* ln1_b = (const float*)d_in[19];
    const float* W1 = (const float*)d_in[20];
    const float* b1 = (const float*)d_in[21];
    const float* W2 = (const float*)d_in[22];
    const float* b2 = (const float*)d_in[23];
    const float* ln2_g = (const float*)d_in[24];
    const float* ln2_b = (const float*)d_in[25];
    const float* att_Wq = (const float*)d_in[26];
    const float* att_Wk = (const float*)d_in[27];

    float *x, *tmp, *sk, *cbias;
    __half *qkv, *w16, *ahi, *alo, *bhi, *blo;
    cudaGetSymbolAddress((void**)&x,     g_x);
    cudaGetSymbolAddress((void**)&qkv,   g_qkv);
    cudaGetSymbolAddress((void**)&tmp,   g_tmp);
    cudaGetSymbolAddress((void**)&sk,    g_sk);
    cudaGetSymbolAddress((void**)&cbias, g_cbias);
    cudaGetSymbolAddress((void**)&w16,   g_w16);
    cudaGetSymbolAddress((void**)&ahi,   g_ahi);
    cudaGetSymbolAddress((void**)&alo,   g_alo);
    cudaGetSymbolAddress((void**)&bhi,   g_bhi);
    cudaGetSymbolAddress((void**)&blo,   g_blo);

    cudaFuncSetAttribute(gemm_mma<0>, cudaFuncAttributeMaxDynamicSharedMemorySize, GEMM_SMEM);
    cudaFuncSetAttribute(gemm_mma<1>, cudaFuncAttributeMaxDynamicSharedMemorySize, GEMM_SMEM);
    cudaFuncSetAttribute(gemm_mma<2>, cudaFuncAttributeMaxDynamicSharedMemorySize, GEMM_SMEM);
    cudaFuncSetAttribute(attn_mma_kernel, cudaFuncAttributeMaxDynamicSharedMemorySize, AT2_SMEM);

    transpose_all_kernel<<<LL*TILES_PER_LAYER, 256>>>(Wq, Wk, Wv, Wo, W1, W2, w16);
    concat_bias_kernel<<<(LL*QKVN + 255)/256, 256>>>(bq, bk, bv, cbias);
    embed_ln_kernel<<<MM, 256>>>(input_ids, type_ids, word_emb, pos_emb,
                                 type_emb, emb_ln_g, emb_ln_b, x, ahi, alo);

    dim3 gQKV(QKVN/128, MM/128);  // (18, 64)
    dim3 gD(DD/128, MM/128);      // (6, 64)
    dim3 gF(FFD/128, MM/128);     // (24, 64)

    for (int l = 0; l < LL; l++) {
        size_t base = (size_t)l * LWSTRIDE;
        const __half* wqkv = w16 + base;
        const __half* wo   = w16 + base + 3*LW_QKVO;
        const __half* w1   = w16 + base + 4*LW_QKVO;
        const __half* w2   = w16 + base + 4*LW_QKVO + LW_FF;

        gemm_mma<1><<<gQKV, 256, GEMM_SMEM>>>(ahi, alo, wqkv, cbias + l*QKVN,
                                              nullptr, qkv, nullptr, QKVN, DD);

        attn_mma_kernel<<<dim3(SS/64, HH, BB), 256, AT2_SMEM>>>(qkv, attn_mask, ahi, alo);

        gemm_mma<0><<<gD, 256, GEMM_SMEM>>>(ahi, alo, wo, nullptr, tmp,
                                            nullptr, nullptr, DD, DD);
        ln_res_kernel<<<MM, 256>>>(x, tmp, bo + l*DD, ln1_g + l*DD, ln1_b + l*DD, ahi, alo);

        gemm_mma<2><<<gF, 256, GEMM_SMEM>>>(ahi, alo, w1, b1 + l*FFD,
                                            nullptr, bhi, blo, FFD, DD);
        gemm_mma<0><<<gD, 256, GEMM_SMEM>>>(bhi, blo, w2, nullptr, tmp,
                                            nullptr, nullptr, DD, FFD);
        ln_res_kernel<<<MM, 256>>>(x, tmp, b2 + l*DD, ln2_g + l*DD, ln2_b + l*DD, ahi, alo);
    }

    sense_k_kernel<<<NSENSE, NATT>>>(sense_emb, att_Wk, sk);
    final_kernel<<<BB, 64>>>(x, location, att_Wq, sk, (float*)d_out);
}

// round 10
// speedup vs baseline: 3.1547x; 1.4487x over previous
#include <cuda_runtime.h>
#include <cuda_fp16.h>
#include <math.h>
#include <stdint.h>

// ---------------------------------------------------------------------------
// Problem constants
// ---------------------------------------------------------------------------
#define BB 32
#define SS 256
#define MM (BB*SS)        // 8192 rows
#define DD 768
#define HH 12
#define DHD 64
#define FFD 3072
#define LL 12
#define NSENSE 64
#define NATT 64
#define QKVN (3*DD)       // 2304

#define LW_QKVO ((size_t)DD*DD)
#define LW_FF   ((size_t)DD*FFD)
#define LWSTRIDE (4*LW_QKVO + 2*LW_FF)

// ---------------------------------------------------------------------------
// Scratch (static __device__ arrays; no runtime allocation allowed)
// ---------------------------------------------------------------------------
__device__ float  g_x  [(size_t)MM*DD];        // residual stream (fp32)
__device__ __half g_qkv[(size_t)MM*QKVN];      // fused QKV output (fp16)
__device__ float  g_tmp[(size_t)MM*DD];        // gemm output before LN
__device__ float  g_sk [NSENSE*NATT];
__device__ float  g_cbias[LL*QKVN];            // concatenated qkv bias

__device__ __half g_w16[LL*LWSTRIDE];          // transposed weights [N,K] fp16
__device__ __half g_ah [(size_t)MM*DD];        // activation fp16
__device__ __half g_bh [(size_t)MM*FFD];       // ffn hidden fp16

// ---------------------------------------------------------------------------
// asm helpers (sm_80-era features, legal on compute_103)
// ---------------------------------------------------------------------------
__device__ __forceinline__ uint32_t smem_to_u32(const void* smem_ptr) {
    uint32_t addr;
    asm("{ .reg .u64 tmp; cvta.to.shared.u64 tmp, %1; cvt.u32.u64 %0, tmp; }"
        : "=r"(addr) : "l"(smem_ptr));
    return addr;
}
#define CP_ASYNC16(dst_u32, src_ptr) \
    asm volatile("cp.async.cg.shared.global [%0], [%1], 16;" \
        :: "r"(dst_u32), "l"(src_ptr))
#define CP_COMMIT asm volatile("cp.async.commit_group;" ::: "memory")
#define CP_WAIT0  asm volatile("cp.async.wait_group 0;" ::: "memory")
#define CP_WAIT1  asm volatile("cp.async.wait_group 1;" ::: "memory")

__device__ __forceinline__ void ldsm_x4(uint32_t addr, uint32_t& r0, uint32_t& r1,
                                        uint32_t& r2, uint32_t& r3) {
    asm volatile("ldmatrix.sync.aligned.m8n8.x4.shared.b16 {%0,%1,%2,%3}, [%4];"
        : "=r"(r0), "=r"(r1), "=r"(r2), "=r"(r3) : "r"(addr));
}
__device__ __forceinline__ void ldsm_x2(uint32_t addr, uint32_t& r0, uint32_t& r1) {
    asm volatile("ldmatrix.sync.aligned.m8n8.x2.shared.b16 {%0,%1}, [%2];"
        : "=r"(r0), "=r"(r1) : "r"(addr));
}
__device__ __forceinline__ void ldsm_x2_trans(uint32_t addr, uint32_t& r0, uint32_t& r1) {
    asm volatile("ldmatrix.sync.aligned.m8n8.x2.trans.shared.b16 {%0,%1}, [%2];"
        : "=r"(r0), "=r"(r1) : "r"(addr));
}
__device__ __forceinline__ void mma_f16(float* c, const uint32_t* a, const uint32_t* b) {
    asm volatile(
        "mma.sync.aligned.m16n8k16.row.col.f32.f16.f16.f32 "
        "{%0,%1,%2,%3}, {%4,%5,%6,%7}, {%8,%9}, {%0,%1,%2,%3};"
        : "+f"(c[0]), "+f"(c[1]), "+f"(c[2]), "+f"(c[3])
        : "r"(a[0]), "r"(a[1]), "r"(a[2]), "r"(a[3]), "r"(b[0]), "r"(b[1]));
}

// ---------------------------------------------------------------------------
// weight prep: ALL transposes in ONE launch.
// ---------------------------------------------------------------------------
#define TILES_PER_LAYER 6912

__global__ __launch_bounds__(256)
void transpose_all_kernel(const float* __restrict__ Wq, const float* __restrict__ Wk,
                          const float* __restrict__ Wv, const float* __restrict__ Wo,
                          const float* __restrict__ W1, const float* __restrict__ W2,
                          __half* __restrict__ w16)
{
    __shared__ float t[32][33];
    int bid = blockIdx.x;
    int l = bid / TILES_PER_LAYER;
    int r = bid % TILES_PER_LAYER;

    const float* src;
    __half* dst;
    int K, N, tilex, tiley;
    size_t base = (size_t)l * LWSTRIDE;

    if (r < 2304) {
        int m = r / 576;
        int tile = r % 576;
        const float* srcs0 = (m == 0) ? Wq : (m == 1) ? Wk : (m == 2) ? Wv : Wo;
        src = srcs0 + (size_t)l * DD * DD;
        dst = w16 + base + (size_t)m * LW_QKVO;
        K = DD; N = DD;
        tilex = tile % 24; tiley = tile / 24;
    } else if (r < 4608) {
        int tile = r - 2304;
        src = W1 + (size_t)l * DD * FFD;
        dst = w16 + base + 4 * LW_QKVO;
        K = DD; N = FFD;
        tilex = tile % 96; tiley = tile / 96;
    } else {
        int tile = r - 4608;
        src = W2 + (size_t)l * FFD * DD;
        dst = w16 + base + 4 * LW_QKVO + LW_FF;
        K = FFD; N = DD;
        tilex = tile % 24; tiley = tile / 24;
    }

    int tx = threadIdx.x & 31, ty = threadIdx.x >> 5;
    int nx = tilex * 32 + tx;
    int ky = tiley * 32;
#pragma unroll
    for (int i = 0; i < 4; i++)
        t[ty + i*8][tx] = src[(size_t)(ky + ty + i*8) * N + nx];
    __syncthreads();
    int kx = tiley * 32 + tx;
    int ny = tilex * 32;
#pragma unroll
    for (int i = 0; i < 4; i++)
        dst[(size_t)(ny + ty + i*8) * K + kx] = __float2half_rn(t[tx][ty + i*8]);
}

__global__ __launch_bounds__(256)
void concat_bias_kernel(const float* __restrict__ bq, const float* __restrict__ bk,
                        const float* __restrict__ bv, float* __restrict__ cb)
{
    int idx = blockIdx.x * 256 + threadIdx.x;
    if (idx >= LL * QKVN) return;
    int l = idx / QKVN, j = idx % QKVN;
    float v;
    if (j < DD)            v = bq[l*DD + j];
    else if (j < 2*DD)     v = bk[l*DD + j - DD];
    else                   v = bv[l*DD + j - 2*DD];
    cb[idx] = v;
}

// ---------------------------------------------------------------------------
// Embedding + LayerNorm -> x fp32 + fp16
// ---------------------------------------------------------------------------
__global__ __launch_bounds__(256)
void embed_ln_kernel(const int* __restrict__ ids, const int* __restrict__ tt,
                     const float* __restrict__ we, const float* __restrict__ pe,
                     const float* __restrict__ te, const float* __restrict__ lg,
                     const float* __restrict__ lb, float* __restrict__ x,
                     __half* __restrict__ xh)
{
    int row = blockIdx.x;
    int s   = row % SS;
    int id  = ids[row];
    int t   = tt[row];
    int tid = threadIdx.x;
    const float* wr = we + (size_t)id * DD;
    const float* pr = pe + (size_t)s  * DD;
    const float* tr = te + (size_t)t  * DD;
    float v[3]; float sum = 0.f, sq = 0.f;
#pragma unroll
    for (int i = 0; i < 3; i++) {
        int d = tid + i * 256;
        float y = wr[d] + pr[d] + tr[d];
        v[i] = y; sum += y; sq += y * y;
    }
    __shared__ float sh1[256], sh2[256];
    sh1[tid] = sum; sh2[tid] = sq;
    __syncthreads();
    for (int st = 128; st > 0; st >>= 1) {
        if (tid < st) { sh1[tid] += sh1[tid+st]; sh2[tid] += sh2[tid+st]; }
        __syncthreads();
    }
    float mu  = sh1[0] * (1.f/768.f);
    float var = fmaxf(sh2[0] * (1.f/768.f) - mu*mu, 0.f);
    float inv = rsqrtf(var + 1e-12f);
#pragma unroll
    for (int i = 0; i < 3; i++) {
        int d = tid + i * 256;
        float y = (v[i]-mu)*inv*lg[d] + lb[d];
        size_t o = (size_t)row*DD + d;
        x[o] = y;
        xh[o] = __float2half_rn(y);
    }
}

// ---------------------------------------------------------------------------
// Residual + bias + LayerNorm -> x fp32 (in place) + fp16
// ---------------------------------------------------------------------------
__global__ __launch_bounds__(256)
void ln_res_kernel(float* __restrict__ x, const float* __restrict__ val,
                   const float* __restrict__ bias, const float* __restrict__ lg,
                   const float* __restrict__ lb, __half* __restrict__ xh)
{
    int row = blockIdx.x;
    int tid = threadIdx.x;
    float v[3]; float sum = 0.f, sq = 0.f;
#pragma unroll
    for (int i = 0; i < 3; i++) {
        int d = tid + i * 256;
        float y = x[(size_t)row*DD + d] + val[(size_t)row*DD + d] + bias[d];
        v[i] = y; sum += y; sq += y * y;
    }
    __shared__ float sh1[256], sh2[256];
    sh1[tid] = sum; sh2[tid] = sq;
    __syncthreads();
    for (int st = 128; st > 0; st >>= 1) {
        if (tid < st) { sh1[tid] += sh1[tid+st]; sh2[tid] += sh2[tid+st]; }
        __syncthreads();
    }
    float mu  = sh1[0] * (1.f/768.f);
    float var = fmaxf(sh2[0] * (1.f/768.f) - mu*mu, 0.f);
    float inv = rsqrtf(var + 1e-12f);
#pragma unroll
    for (int i = 0; i < 3; i++) {
        int d = tid + i * 256;
        float y = (v[i]-mu)*inv*lg[d] + lb[d];
        size_t o = (size_t)row*DD + d;
        x[o] = y;
        xh[o] = __float2half_rn(y);
    }
}

// ---------------------------------------------------------------------------
// HMMA GEMM: C[M,N] = A[M,K] @ Wt[N,K]^T, all-fp16 inputs, fp32 accumulate.
// CTA tile 128x128x32, 8 warps (2m x 4n), mma m16n8k16, 3-stage cp.async.
// MODE 0: C fp32   MODE 1: +bias -> fp16 out   MODE 2: +bias+gelu -> fp16 out
// ---------------------------------------------------------------------------
__device__ __forceinline__ float gelu_exact(float x) {
    return 0.5f * x * (1.0f + erff(x * 0.70710678118654752f));
}

#define GPAD 40
#define TSZB (128*GPAD*2)        // 10240 B per 128x32 fp16 tile
#define STAGEB (2*TSZB)          // A, W (20480 B)
#define NSTAGE 3
#define GEMM_SMEM (NSTAGE*STAGEB)   // 61440 B

__device__ __forceinline__ void gemm_load_stage(
    uint32_t sbase, const __half* __restrict__ A, const __half* __restrict__ W,
    int bm, int bn, int k0, int K, int tid)
{
    const __half* bases[2] = { A, W };
#pragma unroll
    for (int i = 0; i < 4; i++) {
        const int tile = i >> 1;                 // 0..1 (compile-time)
        int f = ((i & 1) << 8) + tid;            // 0..511
        int r  = f >> 2;
        int cq = f & 3;
        int rowg = ((tile == 0) ? bm : bn) + r;
        const __half* src = bases[tile] + (size_t)rowg * K + k0 + cq * 8;
        uint32_t dst = sbase + tile * TSZB + r * (GPAD*2) + cq * 16;
        CP_ASYNC16(dst, src);
    }
}

template<int MODE>
__global__ __launch_bounds__(256)
void gemm_mma(const __half* __restrict__ A, const __half* __restrict__ W,
              const float* __restrict__ bias, float* __restrict__ C,
              __half* __restrict__ Ch, int N, int K)
{
    extern __shared__ char smem[];
    const uint32_t sb = smem_to_u32(smem);
    const int tid  = threadIdx.x;
    const int wid  = tid >> 5;
    const int lane = tid & 31;
    const int wm = wid >> 2;
    const int wn = wid & 3;
    const int bm = blockIdx.y * 128;
    const int bn = blockIdx.x * 128;

    float acc[4][4][4];
#pragma unroll
    for (int mi = 0; mi < 4; mi++)
#pragma unroll
        for (int ni = 0; ni < 4; ni++)
#pragma unroll
            for (int p = 0; p < 4; p++) acc[mi][ni][p] = 0.f;

    const int nchunks = K >> 5;

    gemm_load_stage(sb, A, W, bm, bn, 0, K, tid);
    CP_COMMIT;
    gemm_load_stage(sb + STAGEB, A, W, bm, bn, 32, K, tid);
    CP_COMMIT;

    const int arow = wm * 64 + (lane & 15);
    const int acolh = (lane >> 4) * 8;
    const int brow = wn * 32 + (lane & 7);
    const int bcolh = ((lane >> 3) & 1) * 8;

    for (int c = 0; c < nchunks; c++) {
        if (c + 1 < nchunks) { CP_WAIT1; } else { CP_WAIT0; }
        __syncthreads();
        if (c + 2 < nchunks) {
            int s2 = (c + 2) % NSTAGE;
            gemm_load_stage(sb + s2 * STAGEB, A, W, bm, bn, (c + 2) << 5, K, tid);
            CP_COMMIT;
        }

        const uint32_t st = sb + (c % NSTAGE) * STAGEB;
        const uint32_t aB = st;
        const uint32_t wB = st + TSZB;

#pragma unroll
        for (int kk = 0; kk < 32; kk += 16) {
            uint32_t af[4][4];
#pragma unroll
            for (int mi = 0; mi < 4; mi++) {
                uint32_t off = (uint32_t)((arow + mi*16) * (GPAD*2) + (kk + acolh) * 2);
                ldsm_x4(aB + off, af[mi][0], af[mi][1], af[mi][2], af[mi][3]);
            }
#pragma unroll
            for (int ni = 0; ni < 4; ni++) {
                uint32_t off = (uint32_t)((brow + ni*8) * (GPAD*2) + (kk + bcolh) * 2);
                uint32_t bw[2];
                ldsm_x2(wB + off, bw[0], bw[1]);
#pragma unroll
                for (int mi = 0; mi < 4; mi++)
                    mma_f16(acc[mi][ni], af[mi], bw);
            }
        }
    }

    const int qrow = lane >> 2;
    const int qcol = (lane & 3) * 2;
#pragma unroll
    for (int mi = 0; mi < 4; mi++) {
#pragma unroll
        for (int p = 0; p < 2; p++) {
            int row = bm + wm*64 + mi*16 + qrow + p*8;
#pragma unroll
            for (int ni = 0; ni < 4; ni++) {
                int col = bn + wn*32 + ni*8 + qcol;
                float v0 = acc[mi][ni][p*2 + 0];
                float v1 = acc[mi][ni][p*2 + 1];
                if (MODE >= 1) { v0 += bias[col]; v1 += bias[col+1]; }
                if (MODE == 0) {
                    float2 o; o.x = v0; o.y = v1;
                    *(float2*)&C[(size_t)row * N + col] = o;
                } else {
                    if (MODE == 2) { v0 = gelu_exact(v0); v1 = gelu_exact(v1); }
                    *(__half2*)&Ch[(size_t)row * N + col] =
                        __halves2half2(__float2half_rn(v0), __float2half_rn(v1));
                }
            }
        }
    }
}

// ---------------------------------------------------------------------------
// HMMA attention: block = (64-query tile, h, b), 256 threads (8 warps).
// ---------------------------------------------------------------------------
#define AHS 72
#define SST 264
#define PST 264

#define AT2_MB   0
#define AT2_RED  1024
#define AT2_MX   2048
#define AT2_INV  2304
#define AT2_Q    2560
#define AT2_KV   11776
#define AT2_S    20992
#define AT2_P    88576
#define AT2_SMEM 122368

__global__ __launch_bounds__(256)
void attn_mma_kernel(const __half* __restrict__ qkv, const int* __restrict__ mask,
                     __half* __restrict__ oh)
{
    extern __shared__ char smc[];
    float*  MB  = (float*)(smc + AT2_MB);
    float*  RED = (float*)(smc + AT2_RED);
    float*  MX  = (float*)(smc + AT2_MX);
    float*  INV = (float*)(smc + AT2_INV);
    __half* Qs  = (__half*)(smc + AT2_Q);
    __half* KV  = (__half*)(smc + AT2_KV);
    float*  S   = (float*)(smc + AT2_S);
    __half* P   = (__half*)(smc + AT2_P);
    const uint32_t qb  = smem_to_u32(Qs);
    const uint32_t kvb = smem_to_u32(KV);
    const uint32_t pbb = smem_to_u32(P);

    const int qt = blockIdx.x, h = blockIdx.y, b = blockIdx.z;
    const int tid = threadIdx.x, wid = tid >> 5, lane = tid & 31;
    const int rowbase = b * SS;
    const int q0 = qt * 64;
    const int hoff = h * DHD;
    const int wm = wid >> 2, wn = wid & 3;

    MB[tid] = (1.0f - (float)mask[rowbase + tid]) * -10000.0f;

#pragma unroll
    for (int i = 0; i < 8; i++) {
        int f = tid + i * 256;
        int r = f >> 5, d2 = f & 31;
        *(__half2*)&Qs[r * AHS + d2 * 2] =
            *(const __half2*)&qkv[(size_t)(rowbase + q0 + r) * QKVN + hoff + d2 * 2];
    }
    __syncthreads();

    for (int kc = 0; kc < 4; kc++) {
#pragma unroll
        for (int i = 0; i < 8; i++) {
            int f = tid + i * 256;
            int r = f >> 5, d2 = f & 31;
            *(__half2*)&KV[r * AHS + d2 * 2] =
                *(const __half2*)&qkv[(size_t)(rowbase + kc*64 + r) * QKVN + DD + hoff + d2*2];
        }
        __syncthreads();

        float acc[2][2][4];
#pragma unroll
        for (int mi = 0; mi < 2; mi++)
#pragma unroll
            for (int ni = 0; ni < 2; ni++)
#pragma unroll
                for (int p = 0; p < 4; p++) acc[mi][ni][p] = 0.f;

#pragma unroll
        for (int kk = 0; kk < 64; kk += 16) {
            uint32_t af[2][4];
#pragma unroll
            for (int mi = 0; mi < 2; mi++) {
                uint32_t off = (uint32_t)((wm*32 + mi*16 + (lane&15)) * (AHS*2) + (kk + (lane>>4)*8) * 2);
                ldsm_x4(qb + off, af[mi][0], af[mi][1], af[mi][2], af[mi][3]);
            }
#pragma unroll
            for (int ni = 0; ni < 2; ni++) {
                uint32_t off = (uint32_t)((wn*16 + ni*8 + (lane&7)) * (AHS*2) + (kk + ((lane>>3)&1)*8) * 2);
                uint32_t bf[2];
                ldsm_x2(kvb + off, bf[0], bf[1]);
#pragma unroll
                for (int mi = 0; mi < 2; mi++)
                    mma_f16(acc[mi][ni], af[mi], bf);
            }
        }

        {
            const int qrow = lane >> 2, qcol = (lane & 3) * 2;
#pragma unroll
            for (int mi = 0; mi < 2; mi++)
#pragma unroll
                for (int ni = 0; ni < 2; ni++) {
                    int rl = wm*32 + mi*16 + qrow;
                    int cl = kc*64 + wn*16 + ni*8 + qcol;
                    S[rl*SST + cl]       = acc[mi][ni][0]*0.125f + MB[cl];
                    S[rl*SST + cl+1]     = acc[mi][ni][1]*0.125f + MB[cl+1];
                    S[(rl+8)*SST + cl]   = acc[mi][ni][2]*0.125f + MB[cl];
                    S[(rl+8)*SST + cl+1] = acc[mi][ni][3]*0.125f + MB[cl+1];
                }
        }
        __syncthreads();
    }

    {
        int row = tid >> 2, sub = tid & 3;
        float m = -3.4e38f;
#pragma unroll 8
        for (int i = 0; i < 64; i++) m = fmaxf(m, S[row*SST + sub + i*4]);
        RED[row*4 + sub] = m;
        __syncthreads();
        if (sub == 0)
            MX[row] = fmaxf(fmaxf(RED[row*4], RED[row*4+1]),
                            fmaxf(RED[row*4+2], RED[row*4+3]));
        __syncthreads();
        float mx = MX[row];
        float ssum = 0.f;
#pragma unroll 8
        for (int i = 0; i < 64; i++) {
            int c = sub + i*4;
            float e = __expf(S[row*SST + c] - mx);
            P[row*PST + c] = __float2half_rn(e);
            ssum += e;
        }
        RED[row*4 + sub] = ssum;
        __syncthreads();
        if (sub == 0)
            INV[row] = 1.0f / (RED[row*4] + RED[row*4+1] + RED[row*4+2] + RED[row*4+3]);
        __syncthreads();
    }

    float accO[2][2][4];
#pragma unroll
    for (int mi = 0; mi < 2; mi++)
#pragma unroll
        for (int ni = 0; ni < 2; ni++)
#pragma unroll
            for (int p = 0; p < 4; p++) accO[mi][ni][p] = 0.f;

    for (int kc = 0; kc < 4; kc++) {
#pragma unroll
        for (int i = 0; i < 8; i++) {
            int f = tid + i * 256;
            int r = f >> 5, d2 = f & 31;
            *(__half2*)&KV[r * AHS + d2 * 2] =
                *(const __half2*)&qkv[(size_t)(rowbase + kc*64 + r) * QKVN + 2*DD + hoff + d2*2];
        }
        __syncthreads();
#pragma unroll
        for (int kk = 0; kk < 64; kk += 16) {
            uint32_t af[2][4];
#pragma unroll
            for (int mi = 0; mi < 2; mi++) {
                uint32_t off = (uint32_t)((wm*32 + mi*16 + (lane&15)) * (PST*2) + (kc*64 + kk + (lane>>4)*8) * 2);
                ldsm_x4(pbb + off, af[mi][0], af[mi][1], af[mi][2], af[mi][3]);
            }
#pragma unroll
            for (int ni = 0; ni < 2; ni++) {
                uint32_t off = (uint32_t)((kk + (lane&15)) * (AHS*2) + (wn*16 + ni*8) * 2);
                uint32_t bf[2];
                ldsm_x2_trans(kvb + off, bf[0], bf[1]);
#pragma unroll
                for (int mi = 0; mi < 2; mi++)
                    mma_f16(accO[mi][ni], af[mi], bf);
            }
        }
        __syncthreads();
    }

    {
        const int qrow = lane >> 2, qcol = (lane & 3) * 2;
#pragma unroll
        for (int mi = 0; mi < 2; mi++)
#pragma unroll
            for (int ni = 0; ni < 2; ni++)
#pragma unroll
                for (int p = 0; p < 2; p++) {
                    int rl = wm*32 + mi*16 + qrow + p*8;
                    int cl = wn*16 + ni*8 + qcol;
                    float inv = INV[rl];
                    float y0 = accO[mi][ni][p*2]     * inv;
                    float y1 = accO[mi][ni][p*2 + 1] * inv;
                    size_t ob = (size_t)(rowbase + q0 + rl) * DD + hoff + cl;
                    *(__half2*)&oh[ob] =
                        __halves2half2(__float2half_rn(y0), __float2half_rn(y1));
                }
    }
}

// ---------------------------------------------------------------------------
// sense key projection + final top-2
// ---------------------------------------------------------------------------
__global__ __launch_bounds__(64)
void sense_k_kernel(const float* __restrict__ sense, const float* __restrict__ Wk,
                    float* __restrict__ sk)
{
    int j = blockIdx.x, t = threadIdx.x;
    float s = 0.f;
    for (int d = 0; d < DD; d++)
        s += sense[(size_t)j*DD + d] * Wk[(size_t)d*NATT + t];
    sk[j*NATT + t] = s;
}

__global__ __launch_bounds__(64)
void final_kernel(const float* __restrict__ x, const int* __restrict__ loc,
                  const float* __restrict__ Wq, const float* __restrict__ sk,
                  float* __restrict__ out)
{
    int b = blockIdx.x, t = threadIdx.x;
    __shared__ float pun[DD];
    __shared__ float pq[NATT];
    __shared__ float sc[NSENSE];

    int r = b*SS + loc[b];
    for (int d = t; d < DD; d += 64) pun[d] = x[(size_t)r*DD + d];
    __syncthreads();

    float s = 0.f;
    for (int d = 0; d < DD; d++) s += pun[d] * Wq[(size_t)d*NATT + t];
    pq[t] = s;
    __syncthreads();

    float sv = 0.f;
#pragma unroll
    for (int u = 0; u < NATT; u++) sv += pq[u] * sk[t*NATT + u];
    sc[t] = sv * 0.125f;
    __syncthreads();

    if (t == 0) {
        int i1 = 0; float b1v = sc[0];
        for (int i = 1; i < NSENSE; i++) if (sc[i] > b1v) { b1v = sc[i]; i1 = i; }
        int i2 = -1; float b2v = -3.4e38f;
        for (int i = 0; i < NSENSE; i++) if (i != i1 && sc[i] > b2v) { b2v = sc[i]; i2 = i; }
        out[b*2+0] = (float)i1;
        out[b*2+1] = (float)i2;
    }
}

// ---------------------------------------------------------------------------
// launch
// ---------------------------------------------------------------------------
extern "C" void kernel_launch(void* const* d_in, const int* in_sizes, int n_in,
                              void* d_out, int out_size)
{
    const int*   input_ids = (const int*)  d_in[0];
    const int*   type_ids  = (const int*)  d_in[1];
    const int*   attn_mask = (const int*)  d_in[2];
    const int*   location  = (const int*)  d_in[3];
    const float* sense_emb = (const float*)d_in[4];
    const float* word_emb  = (const float*)d_in[5];
    const float* pos_emb   = (const float*)d_in[6];
    const float* type_emb  = (const float*)d_in[7];
    const float* emb_ln_g  = (const float*)d_in[8];
    const float* emb_ln_b  = (const float*)d_in[9];
    const float* Wq = (const float*)d_in[10];
    const float* bq = (const float*)d_in[11];
    const float* Wk = (const float*)d_in[12];
    const float* bk = (const float*)d_in[13];
    const float* Wv = (const float*)d_in[14];
    const float* bv = (const float*)d_in[15];
    const float* Wo = (const float*)d_in[16];
    const float* bo = (const float*)d_in[17];
    const float* ln1_g = (const float*)d_in[18];
    const float* ln1_b = (const float*)d_in[19];
    const float* W1 = (const float*)d_in[20];
    const float* b1 = (const float*)d_in[21];
    const float* W2 = (const float*)d_in[22];
    const float* b2 = (const float*)d_in[23];
    const float* ln2_g = (const float*)d_in[24];
    const float* ln2_b = (const float*)d_in[25];
    const float* att_Wq = (const float*)d_in[26];
    const float* att_Wk = (const float*)d_in[27];

    float *x, *tmp, *sk, *cbias;
    __half *qkv, *w16, *ah, *bh;
    cudaGetSymbolAddress((void**)&x,     g_x);
    cudaGetSymbolAddress((void**)&qkv,   g_qkv);
    cudaGetSymbolAddress((void**)&tmp,   g_tmp);
    cudaGetSymbolAddress((void**)&sk,    g_sk);
    cudaGetSymbolAddress((void**)&cbias, g_cbias);
    cudaGetSymbolAddress((void**)&w16,   g_w16);
    cudaGetSymbolAddress((void**)&ah,    g_ah);
    cudaGetSymbolAddress((void**)&bh,    g_bh);

    cudaFuncSetAttribute(gemm_mma<0>, cudaFuncAttributeMaxDynamicSharedMemorySize, GEMM_SMEM);
    cudaFuncSetAttribute(gemm_mma<1>, cudaFuncAttributeMaxDynamicSharedMemorySize, GEMM_SMEM);
    cudaFuncSetAttribute(gemm_mma<2>, cudaFuncAttributeMaxDynamicSharedMemorySize, GEMM_SMEM);
    cudaFuncSetAttribute(attn_mma_kernel, cudaFuncAttributeMaxDynamicSharedMemorySize, AT2_SMEM);

    transpose_all_kernel<<<LL*TILES_PER_LAYER, 256>>>(Wq, Wk, Wv, Wo, W1, W2, w16);
    concat_bias_kernel<<<(LL*QKVN + 255)/256, 256>>>(bq, bk, bv, cbias);
    embed_ln_kernel<<<MM, 256>>>(input_ids, type_ids, word_emb, pos_emb,
                                 type_emb, emb_ln_g, emb_ln_b, x, ah);

    dim3 gQKV(QKVN/128, MM/128);  // (18, 64)
    dim3 gD(DD/128, MM/128);      // (6, 64)
    dim3 gF(FFD/128, MM/128);     // (24, 64)

    for (int l = 0; l < LL; l++) {
        size_t base = (size_t)l * LWSTRIDE;
        const __half* wqkv = w16 + base;
        const __half* wo   = w16 + base + 3*LW_QKVO;
        const __half* w1   = w16 + base + 4*LW_QKVO;
        const __half* w2   = w16 + base + 4*LW_QKVO + LW_FF;

        gemm_mma<1><<<gQKV, 256, GEMM_SMEM>>>(ah, wqkv, cbias + l*QKVN,
                                              nullptr, qkv, QKVN, DD);

        attn_mma_kernel<<<dim3(SS/64, HH, BB), 256, AT2_SMEM>>>(qkv, attn_mask, ah);

        gemm_mma<0><<<gD, 256, GEMM_SMEM>>>(ah, wo, nullptr, tmp, nullptr, DD, DD);
        ln_res_kernel<<<MM, 256>>>(x, tmp, bo + l*DD, ln1_g + l*DD, ln1_b + l*DD, ah);

        gemm_mma<2><<<gF, 256, GEMM_SMEM>>>(ah, w1, b1 + l*FFD, nullptr, bh, FFD, DD);
        gemm_mma<0><<<gD, 256, GEMM_SMEM>>>(bh, w2, nullptr, tmp, nullptr, DD, FFD);
        ln_res_kernel<<<MM, 256>>>(x, tmp, b2 + l*DD, ln2_g + l*DD, ln2_b + l*DD, ah);
    }

    sense_k_kernel<<<NSENSE, NATT>>>(sense_emb, att_Wk, sk);
    final_kernel<<<BB, 64>>>(x, location, att_Wq, sk, (float*)d_out);
}

// round 12
// speedup vs baseline: 3.6019x; 1.1418x over previous
#include <cuda_runtime.h>
#include <cuda_fp16.h>
#include <math.h>
#include <stdint.h>

// ---------------------------------------------------------------------------
// Problem constants
// ---------------------------------------------------------------------------
#define BB 32
#define SS 256
#define MM (BB*SS)        // 8192 rows
#define DD 768
#define HH 12
#define DHD 64
#define FFD 3072
#define LL 12
#define NSENSE 64
#define NATT 64
#define QKVN (3*DD)       // 2304

#define LW_QKVO ((size_t)DD*DD)
#define LW_FF   ((size_t)DD*FFD)
#define LWSTRIDE (4*LW_QKVO + 2*LW_FF)

// ---------------------------------------------------------------------------
// Scratch (static __device__ arrays; no runtime allocation allowed)
// ---------------------------------------------------------------------------
__device__ float  g_x  [(size_t)MM*DD];        // residual stream (fp32)
__device__ __half g_qkv[(size_t)MM*QKVN];      // fused QKV output (fp16)
__device__ float  g_tmp[(size_t)MM*DD];        // gemm output before LN
__device__ float  g_sk [NSENSE*NATT];
__device__ float  g_cbias[LL*QKVN];            // concatenated qkv bias

__device__ __half g_w16[LL*LWSTRIDE];          // transposed weights [N,K] fp16
__device__ __half g_ah [(size_t)MM*DD];        // activation fp16
__device__ __half g_bh [(size_t)MM*FFD];       // ffn hidden fp16

// ---------------------------------------------------------------------------
// asm helpers (sm_80-era features, legal on compute_103)
// ---------------------------------------------------------------------------
__device__ __forceinline__ uint32_t smem_to_u32(const void* smem_ptr) {
    uint32_t addr;
    asm("{ .reg .u64 tmp; cvta.to.shared.u64 tmp, %1; cvt.u32.u64 %0, tmp; }"
        : "=r"(addr) : "l"(smem_ptr));
    return addr;
}
#define CP_ASYNC16(dst_u32, src_ptr) \
    asm volatile("cp.async.cg.shared.global [%0], [%1], 16;" \
        :: "r"(dst_u32), "l"(src_ptr))
#define CP_COMMIT asm volatile("cp.async.commit_group;" ::: "memory")
#define CP_WAIT0  asm volatile("cp.async.wait_group 0;" ::: "memory")
#define CP_WAIT1  asm volatile("cp.async.wait_group 1;" ::: "memory")

__device__ __forceinline__ void ldsm_x4(uint32_t addr, uint32_t& r0, uint32_t& r1,
                                        uint32_t& r2, uint32_t& r3) {
    asm volatile("ldmatrix.sync.aligned.m8n8.x4.shared.b16 {%0,%1,%2,%3}, [%4];"
        : "=r"(r0), "=r"(r1), "=r"(r2), "=r"(r3) : "r"(addr));
}
__device__ __forceinline__ void ldsm_x2(uint32_t addr, uint32_t& r0, uint32_t& r1) {
    asm volatile("ldmatrix.sync.aligned.m8n8.x2.shared.b16 {%0,%1}, [%2];"
        : "=r"(r0), "=r"(r1) : "r"(addr));
}
__device__ __forceinline__ void ldsm_x2_trans(uint32_t addr, uint32_t& r0, uint32_t& r1) {
    asm volatile("ldmatrix.sync.aligned.m8n8.x2.trans.shared.b16 {%0,%1}, [%2];"
        : "=r"(r0), "=r"(r1) : "r"(addr));
}
__device__ __forceinline__ void mma_f16(float* c, const uint32_t* a, const uint32_t* b) {
    asm volatile(
        "mma.sync.aligned.m16n8k16.row.col.f32.f16.f16.f32 "
        "{%0,%1,%2,%3}, {%4,%5,%6,%7}, {%8,%9}, {%0,%1,%2,%3};"
        : "+f"(c[0]), "+f"(c[1]), "+f"(c[2]), "+f"(c[3])
        : "r"(a[0]), "r"(a[1]), "r"(a[2]), "r"(a[3]), "r"(b[0]), "r"(b[1]));
}

// ---------------------------------------------------------------------------
// weight prep: ALL transposes in ONE launch.
// ---------------------------------------------------------------------------
#define TILES_PER_LAYER 6912

__global__ __launch_bounds__(256)
void transpose_all_kernel(const float* __restrict__ Wq, const float* __restrict__ Wk,
                          const float* __restrict__ Wv, const float* __restrict__ Wo,
                          const float* __restrict__ W1, const float* __restrict__ W2,
                          __half* __restrict__ w16)
{
    __shared__ float t[32][33];
    int bid = blockIdx.x;
    int l = bid / TILES_PER_LAYER;
    int r = bid % TILES_PER_LAYER;

    const float* src;
    __half* dst;
    int K, N, tilex, tiley;
    size_t base = (size_t)l * LWSTRIDE;

    if (r < 2304) {
        int m = r / 576;
        int tile = r % 576;
        const float* srcs0 = (m == 0) ? Wq : (m == 1) ? Wk : (m == 2) ? Wv : Wo;
        src = srcs0 + (size_t)l * DD * DD;
        dst = w16 + base + (size_t)m * LW_QKVO;
        K = DD; N = DD;
        tilex = tile % 24; tiley = tile / 24;
    } else if (r < 4608) {
        int tile = r - 2304;
        src = W1 + (size_t)l * DD * FFD;
        dst = w16 + base + 4 * LW_QKVO;
        K = DD; N = FFD;
        tilex = tile % 96; tiley = tile / 96;
    } else {
        int tile = r - 4608;
        src = W2 + (size_t)l * FFD * DD;
        dst = w16 + base + 4 * LW_QKVO + LW_FF;
        K = FFD; N = DD;
        tilex = tile % 24; tiley = tile / 24;
    }

    int tx = threadIdx.x & 31, ty = threadIdx.x >> 5;
    int nx = tilex * 32 + tx;
    int ky = tiley * 32;
#pragma unroll
    for (int i = 0; i < 4; i++)
        t[ty + i*8][tx] = src[(size_t)(ky + ty + i*8) * N + nx];
    __syncthreads();
    int kx = tiley * 32 + tx;
    int ny = tilex * 32;
#pragma unroll
    for (int i = 0; i < 4; i++)
        dst[(size_t)(ny + ty + i*8) * K + kx] = __float2half_rn(t[tx][ty + i*8]);
}

__global__ __launch_bounds__(256)
void concat_bias_kernel(const float* __restrict__ bq, const float* __restrict__ bk,
                        const float* __restrict__ bv, float* __restrict__ cb)
{
    int idx = blockIdx.x * 256 + threadIdx.x;
    if (idx >= LL * QKVN) return;
    int l = idx / QKVN, j = idx % QKVN;
    float v;
    if (j < DD)            v = bq[l*DD + j];
    else if (j < 2*DD)     v = bk[l*DD + j - DD];
    else                   v = bv[l*DD + j - 2*DD];
    cb[idx] = v;
}

// ---------------------------------------------------------------------------
// Embedding + LayerNorm -> x fp32 + fp16
// ---------------------------------------------------------------------------
__global__ __launch_bounds__(256)
void embed_ln_kernel(const int* __restrict__ ids, const int* __restrict__ tt,
                     const float* __restrict__ we, const float* __restrict__ pe,
                     const float* __restrict__ te, const float* __restrict__ lg,
                     const float* __restrict__ lb, float* __restrict__ x,
                     __half* __restrict__ xh)
{
    int row = blockIdx.x;
    int s   = row % SS;
    int id  = ids[row];
    int t   = tt[row];
    int tid = threadIdx.x;
    const float* wr = we + (size_t)id * DD;
    const float* pr = pe + (size_t)s  * DD;
    const float* tr = te + (size_t)t  * DD;
    float v[3]; float sum = 0.f, sq = 0.f;
#pragma unroll
    for (int i = 0; i < 3; i++) {
        int d = tid + i * 256;
        float y = wr[d] + pr[d] + tr[d];
        v[i] = y; sum += y; sq += y * y;
    }
    __shared__ float sh1[256], sh2[256];
    sh1[tid] = sum; sh2[tid] = sq;
    __syncthreads();
    for (int st = 128; st > 0; st >>= 1) {
        if (tid < st) { sh1[tid] += sh1[tid+st]; sh2[tid] += sh2[tid+st]; }
        __syncthreads();
    }
    float mu  = sh1[0] * (1.f/768.f);
    float var = fmaxf(sh2[0] * (1.f/768.f) - mu*mu, 0.f);
    float inv = rsqrtf(var + 1e-12f);
#pragma unroll
    for (int i = 0; i < 3; i++) {
        int d = tid + i * 256;
        float y = (v[i]-mu)*inv*lg[d] + lb[d];
        size_t o = (size_t)row*DD + d;
        x[o] = y;
        xh[o] = __float2half_rn(y);
    }
}

// ---------------------------------------------------------------------------
// Residual + bias + LayerNorm -> x fp32 (in place) + fp16
// ---------------------------------------------------------------------------
__global__ __launch_bounds__(256)
void ln_res_kernel(float* __restrict__ x, const float* __restrict__ val,
                   const float* __restrict__ bias, const float* __restrict__ lg,
                   const float* __restrict__ lb, __half* __restrict__ xh)
{
    int row = blockIdx.x;
    int tid = threadIdx.x;
    float v[3]; float sum = 0.f, sq = 0.f;
#pragma unroll
    for (int i = 0; i < 3; i++) {
        int d = tid + i * 256;
        float y = x[(size_t)row*DD + d] + val[(size_t)row*DD + d] + bias[d];
        v[i] = y; sum += y; sq += y * y;
    }
    __shared__ float sh1[256], sh2[256];
    sh1[tid] = sum; sh2[tid] = sq;
    __syncthreads();
    for (int st = 128; st > 0; st >>= 1) {
        if (tid < st) { sh1[tid] += sh1[tid+st]; sh2[tid] += sh2[tid+st]; }
        __syncthreads();
    }
    float mu  = sh1[0] * (1.f/768.f);
    float var = fmaxf(sh2[0] * (1.f/768.f) - mu*mu, 0.f);
    float inv = rsqrtf(var + 1e-12f);
#pragma unroll
    for (int i = 0; i < 3; i++) {
        int d = tid + i * 256;
        float y = (v[i]-mu)*inv*lg[d] + lb[d];
        size_t o = (size_t)row*DD + d;
        x[o] = y;
        xh[o] = __float2half_rn(y);
    }
}

// ---------------------------------------------------------------------------
// HMMA GEMM: C[M,N] = A[M,K] @ Wt[N,K]^T, fp16 inputs, fp32 accumulate.
// CTA tile 128x128x64 (K-chunk 64 -> half the barriers vs 32), 8 warps (2m x 4n),
// mma m16n8k16, 3-stage cp.async pipeline (110.6KB smem, 2 CTAs/SM).
// MODE 0: C fp32   MODE 1: +bias -> fp16 out   MODE 2: +bias+gelu -> fp16 out
// ---------------------------------------------------------------------------
__device__ __forceinline__ float gelu_exact(float x) {
    return 0.5f * x * (1.0f + erff(x * 0.70710678118654752f));
}

#define GK 64                    // k-chunk
#define GPAD 72                  // smem row stride in halves (144 B)
#define TSZB (128*GPAD*2)        // 18432 B per 128x64 fp16 tile
#define STAGEB (2*TSZB)          // A, W (36864 B)
#define NSTAGE 3
#define GEMM_SMEM (NSTAGE*STAGEB)   // 110592 B

__device__ __forceinline__ void gemm_load_stage(
    uint32_t sbase, const __half* __restrict__ A, const __half* __restrict__ W,
    int bm, int bn, int k0, int K, int tid)
{
    const __half* bases[2] = { A, W };
#pragma unroll
    for (int i = 0; i < 8; i++) {
        const int tile = i >> 2;                 // 0..1 (compile-time)
        int f = ((i & 3) << 8) + tid;            // 0..1023
        int r  = f >> 3;                         // 0..127
        int cq = f & 7;                          // 16B chunk within 128B row
        int rowg = ((tile == 0) ? bm : bn) + r;
        const __half* src = bases[tile] + (size_t)rowg * K + k0 + cq * 8;
        uint32_t dst = sbase + tile * TSZB + r * (GPAD*2) + cq * 16;
        CP_ASYNC16(dst, src);
    }
}

template<int MODE>
__global__ __launch_bounds__(256)
void gemm_mma(const __half* __restrict__ A, const __half* __restrict__ W,
              const float* __restrict__ bias, float* __restrict__ C,
              __half* __restrict__ Ch, int N, int K)
{
    extern __shared__ char smem[];
    const uint32_t sb = smem_to_u32(smem);
    const int tid  = threadIdx.x;
    const int wid  = tid >> 5;
    const int lane = tid & 31;
    const int wm = wid >> 2;
    const int wn = wid & 3;
    const int bm = blockIdx.y * 128;
    const int bn = blockIdx.x * 128;

    float acc[4][4][4];
#pragma unroll
    for (int mi = 0; mi < 4; mi++)
#pragma unroll
        for (int ni = 0; ni < 4; ni++)
#pragma unroll
            for (int p = 0; p < 4; p++) acc[mi][ni][p] = 0.f;

    const int nchunks = K / GK;

    gemm_load_stage(sb, A, W, bm, bn, 0, K, tid);
    CP_COMMIT;
    gemm_load_stage(sb + STAGEB, A, W, bm, bn, GK, K, tid);
    CP_COMMIT;

    const int arow = wm * 64 + (lane & 15);
    const int acolh = (lane >> 4) * 8;
    const int brow = wn * 32 + (lane & 7);
    const int bcolh = ((lane >> 3) & 1) * 8;

    for (int c = 0; c < nchunks; c++) {
        if (c + 1 < nchunks) { CP_WAIT1; } else { CP_WAIT0; }
        __syncthreads();
        if (c + 2 < nchunks) {
            int s2 = (c + 2) % NSTAGE;
            gemm_load_stage(sb + s2 * STAGEB, A, W, bm, bn, (c + 2) * GK, K, tid);
            CP_COMMIT;
        }

        const uint32_t st = sb + (c % NSTAGE) * STAGEB;
        const uint32_t aB = st;
        const uint32_t wB = st + TSZB;

#pragma unroll
        for (int kk = 0; kk < GK; kk += 16) {
            uint32_t af[4][4];
#pragma unroll
            for (int mi = 0; mi < 4; mi++) {
                uint32_t off = (uint32_t)((arow + mi*16) * (GPAD*2) + (kk + acolh) * 2);
                ldsm_x4(aB + off, af[mi][0], af[mi][1], af[mi][2], af[mi][3]);
            }
#pragma unroll
            for (int ni = 0; ni < 4; ni++) {
                uint32_t off = (uint32_t)((brow + ni*8) * (GPAD*2) + (kk + bcolh) * 2);
                uint32_t bw[2];
                ldsm_x2(wB + off, bw[0], bw[1]);
#pragma unroll
                for (int mi = 0; mi < 4; mi++)
                    mma_f16(acc[mi][ni], af[mi], bw);
            }
        }
    }

    const int qrow = lane >> 2;
    const int qcol = (lane & 3) * 2;
#pragma unroll
    for (int mi = 0; mi < 4; mi++) {
#pragma unroll
        for (int p = 0; p < 2; p++) {
            int row = bm + wm*64 + mi*16 + qrow + p*8;
#pragma unroll
            for (int ni = 0; ni < 4; ni++) {
                int col = bn + wn*32 + ni*8 + qcol;
                float v0 = acc[mi][ni][p*2 + 0];
                float v1 = acc[mi][ni][p*2 + 1];
                if (MODE >= 1) { v0 += bias[col]; v1 += bias[col+1]; }
                if (MODE == 0) {
                    float2 o; o.x = v0; o.y = v1;
                    *(float2*)&C[(size_t)row * N + col] = o;
                } else {
                    if (MODE == 2) { v0 = gelu_exact(v0); v1 = gelu_exact(v1); }
                    *(__half2*)&Ch[(size_t)row * N + col] =
                        __halves2half2(__float2half_rn(v0), __float2half_rn(v1));
                }
            }
        }
    }
}

// ---------------------------------------------------------------------------
// HMMA attention: block = (64-query tile, h, b), 256 threads (8 warps).
// ---------------------------------------------------------------------------
#define AHS 72
#define SST 264
#define PST 264

#define AT2_MB   0
#define AT2_RED  1024
#define AT2_MX   2048
#define AT2_INV  2304
#define AT2_Q    2560
#define AT2_KV   11776
#define AT2_S    20992
#define AT2_P    88576
#define AT2_SMEM 122368

__global__ __launch_bounds__(256)
void attn_mma_kernel(const __half* __restrict__ qkv, const int* __restrict__ mask,
                     __half* __restrict__ oh)
{
    extern __shared__ char smc[];
    float*  MB  = (float*)(smc + AT2_MB);
    float*  RED = (float*)(smc + AT2_RED);
    float*  MX  = (float*)(smc + AT2_MX);
    float*  INV = (float*)(smc + AT2_INV);
    __half* Qs  = (__half*)(smc + AT2_Q);
    __half* KV  = (__half*)(smc + AT2_KV);
    float*  S   = (float*)(smc + AT2_S);
    __half* P   = (__half*)(smc + AT2_P);
    const uint32_t qb  = smem_to_u32(Qs);
    const uint32_t kvb = smem_to_u32(KV);
    const uint32_t pbb = smem_to_u32(P);

    const int qt = blockIdx.x, h = blockIdx.y, b = blockIdx.z;
    const int tid = threadIdx.x, wid = tid >> 5, lane = tid & 31;
    const int rowbase = b * SS;
    const int q0 = qt * 64;
    const int hoff = h * DHD;
    const int wm = wid >> 2, wn = wid & 3;

    MB[tid] = (1.0f - (float)mask[rowbase + tid]) * -10000.0f;

#pragma unroll
    for (int i = 0; i < 8; i++) {
        int f = tid + i * 256;
        int r = f >> 5, d2 = f & 31;
        *(__half2*)&Qs[r * AHS + d2 * 2] =
            *(const __half2*)&qkv[(size_t)(rowbase + q0 + r) * QKVN + hoff + d2 * 2];
    }
    __syncthreads();

    for (int kc = 0; kc < 4; kc++) {
#pragma unroll
        for (int i = 0; i < 8; i++) {
            int f = tid + i * 256;
            int r = f >> 5, d2 = f & 31;
            *(__half2*)&KV[r * AHS + d2 * 2] =
                *(const __half2*)&qkv[(size_t)(rowbase + kc*64 + r) * QKVN + DD + hoff + d2*2];
        }
        __syncthreads();

        float acc[2][2][4];
#pragma unroll
        for (int mi = 0; mi < 2; mi++)
#pragma unroll
            for (int ni = 0; ni < 2; ni++)
#pragma unroll
                for (int p = 0; p < 4; p++) acc[mi][ni][p] = 0.f;

#pragma unroll
        for (int kk = 0; kk < 64; kk += 16) {
            uint32_t af[2][4];
#pragma unroll
            for (int mi = 0; mi < 2; mi++) {
                uint32_t off = (uint32_t)((wm*32 + mi*16 + (lane&15)) * (AHS*2) + (kk + (lane>>4)*8) * 2);
                ldsm_x4(qb + off, af[mi][0], af[mi][1], af[mi][2], af[mi][3]);
            }
#pragma unroll
            for (int ni = 0; ni < 2; ni++) {
                uint32_t off = (uint32_t)((wn*16 + ni*8 + (lane&7)) * (AHS*2) + (kk + ((lane>>3)&1)*8) * 2);
                uint32_t bf[2];
                ldsm_x2(kvb + off, bf[0], bf[1]);
#pragma unroll
                for (int mi = 0; mi < 2; mi++)
                    mma_f16(acc[mi][ni], af[mi], bf);
            }
        }

        {
            const int qrow = lane >> 2, qcol = (lane & 3) * 2;
#pragma unroll
            for (int mi = 0; mi < 2; mi++)
#pragma unroll
                for (int ni = 0; ni < 2; ni++) {
                    int rl = wm*32 + mi*16 + qrow;
                    int cl = kc*64 + wn*16 + ni*8 + qcol;
                    S[rl*SST + cl]       = acc[mi][ni][0]*0.125f + MB[cl];
                    S[rl*SST + cl+1]     = acc[mi][ni][1]*0.125f + MB[cl+1];
                    S[(rl+8)*SST + cl]   = acc[mi][ni][2]*0.125f + MB[cl];
                    S[(rl+8)*SST + cl+1] = acc[mi][ni][3]*0.125f + MB[cl+1];
                }
        }
        __syncthreads();
    }

    {
        int row = tid >> 2, sub = tid & 3;
        float m = -3.4e38f;
#pragma unroll 8
        for (int i = 0; i < 64; i++) m = fmaxf(m, S[row*SST + sub + i*4]);
        RED[row*4 + sub] = m;
        __syncthreads();
        if (sub == 0)
            MX[row] = fmaxf(fmaxf(RED[row*4], RED[row*4+1]),
                            fmaxf(RED[row*4+2], RED[row*4+3]));
        __syncthreads();
        float mx = MX[row];
        float ssum = 0.f;
#pragma unroll 8
        for (int i = 0; i < 64; i++) {
            int c = sub + i*4;
            float e = __expf(S[row*SST + c] - mx);
            P[row*PST + c] = __float2half_rn(e);
            ssum += e;
        }
        RED[row*4 + sub] = ssum;
        __syncthreads();
        if (sub == 0)
            INV[row] = 1.0f / (RED[row*4] + RED[row*4+1] + RED[row*4+2] + RED[row*4+3]);
        __syncthreads();
    }

    float accO[2][2][4];
#pragma unroll
    for (int mi = 0; mi < 2; mi++)
#pragma unroll
        for (int ni = 0; ni < 2; ni++)
#pragma unroll
            for (int p = 0; p < 4; p++) accO[mi][ni][p] = 0.f;

    for (int kc = 0; kc < 4; kc++) {
#pragma unroll
        for (int i = 0; i < 8; i++) {
            int f = tid + i * 256;
            int r = f >> 5, d2 = f & 31;
            *(__half2*)&KV[r * AHS + d2 * 2] =
                *(const __half2*)&qkv[(size_t)(rowbase + kc*64 + r) * QKVN + 2*DD + hoff + d2*2];
        }
        __syncthreads();
#pragma unroll
        for (int kk = 0; kk < 64; kk += 16) {
            uint32_t af[2][4];
#pragma unroll
            for (int mi = 0; mi < 2; mi++) {
                uint32_t off = (uint32_t)((wm*32 + mi*16 + (lane&15)) * (PST*2) + (kc*64 + kk + (lane>>4)*8) * 2);
                ldsm_x4(pbb + off, af[mi][0], af[mi][1], af[mi][2], af[mi][3]);
            }
#pragma unroll
            for (int ni = 0; ni < 2; ni++) {
                uint32_t off = (uint32_t)((kk + (lane&15)) * (AHS*2) + (wn*16 + ni*8) * 2);
                uint32_t bf[2];
                ldsm_x2_trans(kvb + off, bf[0], bf[1]);
#pragma unroll
                for (int mi = 0; mi < 2; mi++)
                    mma_f16(accO[mi][ni], af[mi], bf);
            }
        }
        __syncthreads();
    }

    {
        const int qrow = lane >> 2, qcol = (lane & 3) * 2;
#pragma unroll
        for (int mi = 0; mi < 2; mi++)
#pragma unroll
            for (int ni = 0; ni < 2; ni++)
#pragma unroll
                for (int p = 0; p < 2; p++) {
                    int rl = wm*32 + mi*16 + qrow + p*8;
                    int cl = wn*16 + ni*8 + qcol;
                    float inv = INV[rl];
                    float y0 = accO[mi][ni][p*2]     * inv;
                    float y1 = accO[mi][ni][p*2 + 1] * inv;
                    size_t ob = (size_t)(rowbase + q0 + rl) * DD + hoff + cl;
                    *(__half2*)&oh[ob] =
                        __halves2half2(__float2half_rn(y0), __float2half_rn(y1));
                }
    }
}

// ---------------------------------------------------------------------------
// sense key projection + final top-2
// ---------------------------------------------------------------------------
__global__ __launch_bounds__(64)
void sense_k_kernel(const float* __restrict__ sense, const float* __restrict__ Wk,
                    float* __restrict__ sk)
{
    int j = blockIdx.x, t = threadIdx.x;
    float s = 0.f;
    for (int d = 0; d < DD; d++)
        s += sense[(size_t)j*DD + d] * Wk[(size_t)d*NATT + t];
    sk[j*NATT + t] = s;
}

__global__ __launch_bounds__(64)
void final_kernel(const float* __restrict__ x, const int* __restrict__ loc,
                  const float* __restrict__ Wq, const float* __restrict__ sk,
                  float* __restrict__ out)
{
    int b = blockIdx.x, t = threadIdx.x;
    __shared__ float pun[DD];
    __shared__ float pq[NATT];
    __shared__ float sc[NSENSE];

    int r = b*SS + loc[b];
    for (int d = t; d < DD; d += 64) pun[d] = x[(size_t)r*DD + d];
    __syncthreads();

    float s = 0.f;
    for (int d = 0; d < DD; d++) s += pun[d] * Wq[(size_t)d*NATT + t];
    pq[t] = s;
    __syncthreads();

    float sv = 0.f;
#pragma unroll
    for (int u = 0; u < NATT; u++) sv += pq[u] * sk[t*NATT + u];
    sc[t] = sv * 0.125f;
    __syncthreads();

    if (t == 0) {
        int i1 = 0; float b1v = sc[0];
        for (int i = 1; i < NSENSE; i++) if (sc[i] > b1v) { b1v = sc[i]; i1 = i; }
        int i2 = -1; float b2v = -3.4e38f;
        for (int i = 0; i < NSENSE; i++) if (i != i1 && sc[i] > b2v) { b2v = sc[i]; i2 = i; }
        out[b*2+0] = (float)i1;
        out[b*2+1] = (float)i2;
    }
}

// ---------------------------------------------------------------------------
// launch
// ---------------------------------------------------------------------------
extern "C" void kernel_launch(void* const* d_in, const int* in_sizes, int n_in,
                              void* d_out, int out_size)
{
    const int*   input_ids = (const int*)  d_in[0];
    const int*   type_ids  = (const int*)  d_in[1];
    const int*   attn_mask = (const int*)  d_in[2];
    const int*   location  = (const int*)  d_in[3];
    const float* sense_emb = (const float*)d_in[4];
    const float* word_emb  = (const float*)d_in[5];
    const float* pos_emb   = (const float*)d_in[6];
    const float* type_emb  = (const float*)d_in[7];
    const float* emb_ln_g  = (const float*)d_in[8];
    const float* emb_ln_b  = (const float*)d_in[9];
    const float* Wq = (const float*)d_in[10];
    const float* bq = (const float*)d_in[11];
    const float* Wk = (const float*)d_in[12];
    const float* bk = (const float*)d_in[13];
    const float* Wv = (const float*)d_in[14];
    const float* bv = (const float*)d_in[15];
    const float* Wo = (const float*)d_in[16];
    const float* bo = (const float*)d_in[17];
    const float* ln1_g = (const float*)d_in[18];
    const float* ln1_b = (const float*)d_in[19];
    const float* W1 = (const float*)d_in[20];
    const float* b1 = (const float*)d_in[21];
    const float* W2 = (const float*)d_in[22];
    const float* b2 = (const float*)d_in[23];
    const float* ln2_g = (const float*)d_in[24];
    const float* ln2_b = (const float*)d_in[25];
    const float* att_Wq = (const float*)d_in[26];
    const float* att_Wk = (const float*)d_in[27];

    float *x, *tmp, *sk, *cbias;
    __half *qkv, *w16, *ah, *bh;
    cudaGetSymbolAddress((void**)&x,     g_x);
    cudaGetSymbolAddress((void**)&qkv,   g_qkv);
    cudaGetSymbolAddress((void**)&tmp,   g_tmp);
    cudaGetSymbolAddress((void**)&sk,    g_sk);
    cudaGetSymbolAddress((void**)&cbias, g_cbias);
    cudaGetSymbolAddress((void**)&w16,   g_w16);
    cudaGetSymbolAddress((void**)&ah,    g_ah);
    cudaGetSymbolAddress((void**)&bh,    g_bh);

    cudaFuncSetAttribute(gemm_mma<0>, cudaFuncAttributeMaxDynamicSharedMemorySize, GEMM_SMEM);
    cudaFuncSetAttribute(gemm_mma<1>, cudaFuncAttributeMaxDynamicSharedMemorySize, GEMM_SMEM);
    cudaFuncSetAttribute(gemm_mma<2>, cudaFuncAttributeMaxDynamicSharedMemorySize, GEMM_SMEM);
    cudaFuncSetAttribute(attn_mma_kernel, cudaFuncAttributeMaxDynamicSharedMemorySize, AT2_SMEM);

    transpose_all_kernel<<<LL*TILES_PER_LAYER, 256>>>(Wq, Wk, Wv, Wo, W1, W2, w16);
    concat_bias_kernel<<<(LL*QKVN + 255)/256, 256>>>(bq, bk, bv, cbias);
    embed_ln_kernel<<<MM, 256>>>(input_ids, type_ids, word_emb, pos_emb,
                                 type_emb, emb_ln_g, emb_ln_b, x, ah);

    dim3 gQKV(QKVN/128, MM/128);  // (18, 64)
    dim3 gD(DD/128, MM/128);      // (6, 64)
    dim3 gF(FFD/128, MM/128);     // (24, 64)

    for (int l = 0; l < LL; l++) {
        size_t base = (size_t)l * LWSTRIDE;
        const __half* wqkv = w16 + base;
        const __half* wo   = w16 + base + 3*LW_QKVO;
        const __half* w1   = w16 + base + 4*LW_QKVO;
        const __half* w2   = w16 + base + 4*LW_QKVO + LW_FF;

        gemm_mma<1><<<gQKV, 256, GEMM_SMEM>>>(ah, wqkv, cbias + l*QKVN,
                                              nullptr, qkv, QKVN, DD);

        attn_mma_kernel<<<dim3(SS/64, HH, BB), 256, AT2_SMEM>>>(qkv, attn_mask, ah);

        gemm_mma<0><<<gD, 256, GEMM_SMEM>>>(ah, wo, nullptr, tmp, nullptr, DD, DD);
        ln_res_kernel<<<MM, 256>>>(x, tmp, bo + l*DD, ln1_g + l*DD, ln1_b + l*DD, ah);

        gemm_mma<2><<<gF, 256, GEMM_SMEM>>>(ah, w1, b1 + l*FFD, nullptr, bh, FFD, DD);
        gemm_mma<0><<<gD, 256, GEMM_SMEM>>>(bh, w2, nullptr, tmp, nullptr, DD, FFD);
        ln_res_kernel<<<MM, 256>>>(x, tmp, b2 + l*DD, ln2_g + l*DD, ln2_b + l*DD, ah);
    }

    sense_k_kernel<<<NSENSE, NATT>>>(sense_emb, att_Wk, sk);
    final_kernel<<<BB, 64>>>(x, location, att_Wq, sk, (float*)d_out);
}